// round 7
// baseline (speedup 1.0000x reference)
#include <cuda_runtime.h>
#include <cuda_bf16.h>
#include <cuda_fp8.h>
#include <mma.h>
#include <math.h>
#include <stdint.h>

using namespace nvcuda;

// Problem constants
#define S_    2048
#define B_    16
#define H_    512
#define L_    4096
#define LAB_  256
#define V_    32000

// fp8 scales
#define SCALE_A 64.0f
#define SCALE_B 512.0f
#define INV_SCALE (1.0f / (SCALE_A * SCALE_B))

// cls tiling
#define CLS_BM   128
#define CLS_BN   128
#define CLS_VT   25
#define NSPLIT   10              // 10 * 25 * 128 = 32000
#define VCHUNK   (CLS_VT * CLS_BN)
#define NSTAGES  (CLS_VT * 8)    // 200 stages of K=32

// cls smem (bytes)
#define AS_LDB   272             // A row stride (256 fp8 + 16 pad), 16B aligned
#define BS_LDB   48              // B row stride (32 fp8 + 16 pad)
#define CLS_A_OFF 0
#define CLS_A_BYTES (CLS_BM * AS_LDB)          // 34816
#define CLS_B_OFF  CLS_A_BYTES
#define CLS_B_TILE (128 * BS_LDB)              // 6144 (128 v-rows x 32 k fp8)
#define CLS_B_BYTES (4 * CLS_B_TILE)           // 24576
#define CLS_RED_OFF (CLS_B_OFF + CLS_B_BYTES)  // 59392
#define CLS_SMEM (CLS_RED_OFF + 128 * 4)       // 59904

// wgemm smem
#define CS_LD 68
#define WG_AS_BYTES (128 * 72 * 2)
#define WG_BS_OFF   WG_AS_BYTES
#define WG_SMEM_BYTES 35840

// Scratch (static device globals)
__device__ __nv_bfloat16 g_spanb[(size_t)L_ * 3 * H_];
__device__ __nv_bfloat16 g_h1b[(size_t)L_ * LAB_];
__device__ float g_feat[(size_t)L_ * LAB_];
__device__ uint8_t g_feat8[(size_t)L_ * LAB_];          // feat * 64 (e4m3)
__device__ __nv_bfloat16 g_w1b[(size_t)3 * H_ * LAB_];
__device__ __nv_bfloat16 g_w2b[(size_t)LAB_ * LAB_];
__device__ uint8_t g_wot8[(size_t)V_ * LAB_];           // Wo^T * 512 (e4m3) [V][256]
__device__ float g_partial[(size_t)L_ * NSPLIT];

// ---------------------------------------------------------------------------
// PTX primitives
// ---------------------------------------------------------------------------
__device__ __forceinline__ uint32_t smem_u32(const void* p) {
    uint32_t a;
    asm("{ .reg .u64 t; cvta.to.shared.u64 t, %1; cvt.u32.u64 %0, t; }"
        : "=r"(a) : "l"(p));
    return a;
}
__device__ __forceinline__ void ldsm_x4(uint32_t r[4], uint32_t addr) {
    asm volatile("ldmatrix.sync.aligned.m8n8.x4.shared.b16 {%0,%1,%2,%3}, [%4];"
        : "=r"(r[0]), "=r"(r[1]), "=r"(r[2]), "=r"(r[3]) : "r"(addr));
}
__device__ __forceinline__ void mma_fp8(float d[4], const uint32_t a[4],
                                        uint32_t b0, uint32_t b1) {
    asm volatile(
        "mma.sync.aligned.m16n8k32.row.col.f32.e4m3.e4m3.f32 "
        "{%0,%1,%2,%3}, {%4,%5,%6,%7}, {%8,%9}, {%0,%1,%2,%3};"
        : "+f"(d[0]), "+f"(d[1]), "+f"(d[2]), "+f"(d[3])
        : "r"(a[0]), "r"(a[1]), "r"(a[2]), "r"(a[3]), "r"(b0), "r"(b1));
}
#define CP_ASYNC16(dst, src) \
    asm volatile("cp.async.cg.shared.global [%0], [%1], 16;" \
        :: "r"(dst), "l"(src) : "memory")
#define CP_COMMIT() asm volatile("cp.async.commit_group;" ::: "memory")
#define CP_WAIT2()  asm volatile("cp.async.wait_group 2;" ::: "memory")
#define CP_WAITALL() asm volatile("cp.async.wait_group 0;" ::: "memory")

__device__ __forceinline__ float ex2f(float x) {
    float r;
    asm("ex2.approx.f32 %0, %1;" : "=f"(r) : "f"(x));
    return r;
}
__device__ __forceinline__ uint8_t to_e4m3(float v) {
    return (uint8_t)__nv_cvt_float_to_fp8(v, __NV_SATFINITE, __NV_E4M3);
}

// ---------------------------------------------------------------------------
// fast exp poly (sigmoid epilogue in wgemm)
// ---------------------------------------------------------------------------
__device__ __forceinline__ float fast_exp(float x) {
    float z = x * 1.4426950408889634f;
    float r = rintf(z);
    float f = z - r;
    float p = 1.3333558146428443e-3f;
    p = fmaf(p, f, 9.6181291976036120e-3f);
    p = fmaf(p, f, 5.5504108664821580e-2f);
    p = fmaf(p, f, 2.4022650695910072e-1f);
    p = fmaf(p, f, 6.9314718055994531e-1f);
    p = fmaf(p, f, 1.0f);
    return __int_as_float(((int)r + 127) << 23) * p;
}

// ---------------------------------------------------------------------------
// span embeddings -> bf16 (float4 vectorized, 128 threads)
// ---------------------------------------------------------------------------
__global__ void span_kernel(const float* __restrict__ hidden,
                            const int* __restrict__ begins,
                            const int* __restrict__ ends,
                            const int* __restrict__ bids) {
    const int l = blockIdx.x;
    const int beg = begins[l];
    const int end = ends[l];
    const int b   = bids[l];
    const float inv_len = 1.0f / (float)(end - beg);
    const float4* hp = (const float4*)hidden;
    const int h4 = threadIdx.x;
    const int H4 = H_ / 4;

    float4 left  = hp[((size_t)(beg - 1) * B_ + b) * H4 + h4];
    float4 right = hp[((size_t)end * B_ + b) * H4 + h4];
    float4 s = make_float4(0.f, 0.f, 0.f, 0.f);
    for (int t = beg; t < end; ++t) {
        float4 v = hp[((size_t)t * B_ + b) * H4 + h4];
        s.x += v.x; s.y += v.y; s.z += v.z; s.w += v.w;
    }
    __nv_bfloat16* out = g_spanb + (size_t)l * (3 * H_);
    uint2 pk;
    pk.x = __nv_bfloat162_raw(__floats2bfloat162_rn(left.x, left.y)).x;
    pk.y = __nv_bfloat162_raw(__floats2bfloat162_rn(left.z, left.w)).x;
    *(uint2*)&out[h4 * 4] = pk;
    pk.x = __nv_bfloat162_raw(__floats2bfloat162_rn(s.x * inv_len, s.y * inv_len)).x;
    pk.y = __nv_bfloat162_raw(__floats2bfloat162_rn(s.z * inv_len, s.w * inv_len)).x;
    *(uint2*)&out[H_ + h4 * 4] = pk;
    pk.x = __nv_bfloat162_raw(__floats2bfloat162_rn(right.x, right.y)).x;
    pk.y = __nv_bfloat162_raw(__floats2bfloat162_rn(right.z, right.w)).x;
    *(uint2*)&out[2 * H_ + h4 * 4] = pk;
}

// ---------------------------------------------------------------------------
// fp32 -> bf16 conversion (W1, W2)
// ---------------------------------------------------------------------------
__global__ void cvt_kernel(const float* __restrict__ src,
                           __nv_bfloat16* __restrict__ dst, int n4) {
    int i = blockIdx.x * blockDim.x + threadIdx.x;
    if (i < n4) {
        float4 v = ((const float4*)src)[i];
        ((__nv_bfloat162*)dst)[2 * i]     = __floats2bfloat162_rn(v.x, v.y);
        ((__nv_bfloat162*)dst)[2 * i + 1] = __floats2bfloat162_rn(v.z, v.w);
    }
}

// ---------------------------------------------------------------------------
// Wo [256][32000] f32 -> WoT8 [32000][256] e4m3 * SCALE_B
// ---------------------------------------------------------------------------
__global__ void wo8_kernel(const float* __restrict__ Wo,
                           uint8_t* __restrict__ WoT8) {
    __shared__ float tile[32][33];
    int v0 = blockIdx.x * 32, k0 = blockIdx.y * 32;
    int tx = threadIdx.x, ty = threadIdx.y;
#pragma unroll
    for (int i = ty; i < 32; i += 8)
        tile[i][tx] = Wo[(size_t)(k0 + i) * V_ + v0 + tx];
    __syncthreads();
#pragma unroll
    for (int i = ty; i < 32; i += 8)
        WoT8[(size_t)(v0 + i) * LAB_ + k0 + tx] =
            to_e4m3(tile[tx][i] * SCALE_B);
}

// ---------------------------------------------------------------------------
// bf16 wmma GEMM for GEMM1/GEMM2
// EPI 1: sigmoid -> bf16. EPI 2: bias -> fp32 g_feat + e4m3 g_feat8 (*64)
// ---------------------------------------------------------------------------
template<int K, int EPI>
__global__ __launch_bounds__(256)
void wgemm_kernel(const __nv_bfloat16* __restrict__ A,
                  const __nv_bfloat16* __restrict__ B,
                  const float* __restrict__ bias,
                  float* __restrict__ C32,
                  __nv_bfloat16* __restrict__ Cb, int N) {
    extern __shared__ char smem[];
    __nv_bfloat16* As = (__nv_bfloat16*)smem;
    __nv_bfloat16* Bs = (__nv_bfloat16*)(smem + WG_BS_OFF);
    float* Cs = (float*)smem;

    const int tid = threadIdx.x;
    const int wid = tid >> 5;
    const int lane = tid & 31;
    const int m0 = blockIdx.x * 128;
    const int n0 = blockIdx.y * 64;

    wmma::fragment<wmma::accumulator, 16, 16, 16, float> acc[4];
#pragma unroll
    for (int j = 0; j < 4; ++j) wmma::fill_fragment(acc[j], 0.0f);

    for (int k0 = 0; k0 < K; k0 += 64) {
        __syncthreads();
#pragma unroll
        for (int t = tid; t < 128 * 8; t += 256) {
            int m = t >> 3, k8 = t & 7;
            uint4 v = *(const uint4*)&A[(size_t)(m0 + m) * K + k0 + k8 * 8];
            *(uint4*)&As[m * 72 + k8 * 8] = v;
        }
#pragma unroll
        for (int t = tid; t < 64 * 8; t += 256) {
            int k = t >> 3, n8 = t & 7;
            uint4 v = *(const uint4*)&B[(size_t)(k0 + k) * N + n0 + n8 * 8];
            *(uint4*)&Bs[k * 72 + n8 * 8] = v;
        }
        __syncthreads();
#pragma unroll
        for (int ks = 0; ks < 4; ++ks) {
            wmma::fragment<wmma::matrix_a, 16, 16, 16, __nv_bfloat16, wmma::row_major> af;
            wmma::load_matrix_sync(af, &As[(wid * 16) * 72 + ks * 16], 72);
#pragma unroll
            for (int nt = 0; nt < 4; ++nt) {
                wmma::fragment<wmma::matrix_b, 16, 16, 16, __nv_bfloat16, wmma::row_major> bf;
                wmma::load_matrix_sync(bf, &Bs[(ks * 16) * 72 + nt * 16], 72);
                wmma::mma_sync(acc[nt], af, bf, acc[nt]);
            }
        }
    }
    __syncthreads();

    float* Cw = Cs + wid * 16 * CS_LD;
#pragma unroll
    for (int nt = 0; nt < 4; ++nt)
        wmma::store_matrix_sync(&Cw[nt * 16], acc[nt], CS_LD, wmma::mem_row_major);
    __syncwarp();

#pragma unroll
    for (int e = 0; e < 32; ++e) {
        int idx = lane + e * 32;
        int r = idx >> 6, c = idx & 63;
        int gr = m0 + wid * 16 + r;
        int gc = n0 + c;
        float v = Cw[r * CS_LD + c] + bias[gc];
        if (EPI == 1) {
            v = 1.0f / (1.0f + fast_exp(-v));
            Cb[(size_t)gr * N + gc] = __float2bfloat16(v);
        } else {
            C32[(size_t)gr * N + gc] = v;
            g_feat8[(size_t)gr * N + gc] = to_e4m3(v * SCALE_A);
        }
    }
}

// ---------------------------------------------------------------------------
// cls: fp8 mma.sync classifier GEMM + fused per-row exp-sums.
// A = feat8 [128][256] (smem rows 272B); B = WoT8 tiles 128v x 32k (rows 48B),
// 4-stage cp.async ring. Per K=32 step: 4 A-ldsm + 2 B-ldsm + 16 fp8 mma.
// 8 warps: wm = wid>>2 (2 x 64 rows), wn = wid&3 (4 x 32 cols).
// grid (L/128 = 32, NSPLIT = 10)
// ---------------------------------------------------------------------------
__global__ __launch_bounds__(256, 2)
void cls_kernel(const float* __restrict__ bo) {
    extern __shared__ char smem[];
    const uint32_t sb = smem_u32(smem);
    float* red = (float*)(smem + CLS_RED_OFF);

    const int tid = threadIdx.x;
    const int wid = tid >> 5;
    const int lane = tid & 31;
    const int wm = wid >> 2;
    const int wn = wid & 3;
    const int l0 = blockIdx.x * CLS_BM;
    const int v_base = blockIdx.y * VCHUNK;
    const float LOG2E = 1.4426950408889634f;
    const float K2 = LOG2E * INV_SCALE;   // descale folded into exp arg

    // Stage A: 128 rows x 256 fp8 -> rows of AS_LDB
    {
        const uint8_t* src = g_feat8 + (size_t)l0 * LAB_;
#pragma unroll
        for (int t = tid; t < 128 * 16; t += 256) {
            int r = t >> 4, c16 = t & 15;
            uint4 v = *(const uint4*)&src[(size_t)r * LAB_ + c16 * 16];
            *(uint4*)(smem + CLS_A_OFF + r * AS_LDB + c16 * 16) = v;
        }
    }
    if (tid < 128) red[tid] = 0.0f;

    // B cp.async: 256 x 16B chunks per stage, 1 per thread
    const int brow = tid >> 1;          // v row 0..127
    const int boff = (tid & 1) * 16;    // 16B half of the 32B k chunk

    // A ldmatrix bases (per m16 tile): rows lane&15, 16B half lane>>4
    uint32_t aBase[4];
#pragma unroll
    for (int mi = 0; mi < 4; ++mi)
        aBase[mi] = sb + CLS_A_OFF
                  + (wm * 64 + mi * 16 + (lane & 15)) * AS_LDB
                  + (lane >> 4) * 16;
    // B ldmatrix bases (per 16-row group): x4 = [n0-7 klo, n0-7 khi, n8-15 klo, n8-15 khi]
    uint32_t bBase[2];
#pragma unroll
    for (int ng = 0; ng < 2; ++ng)
        bBase[ng] = sb + CLS_B_OFF
                  + (wn * 32 + ng * 16 + (lane >> 4) * 8 + (lane & 7)) * BS_LDB
                  + ((lane >> 3) & 1) * 16;

    auto issue_stage = [&](int st) {
        const int k0 = (st & 7) * 32;
        const int v0 = v_base + (st >> 3) * CLS_BN;
        const uint8_t* src = g_wot8 + (size_t)(v0 + brow) * LAB_ + k0 + boff;
        const uint32_t dst = sb + CLS_B_OFF + (st & 3) * CLS_B_TILE
                           + brow * BS_LDB + boff;
        CP_ASYNC16(dst, (const char*)src);
    };

#pragma unroll
    for (int st = 0; st < 3; ++st) { issue_stage(st); CP_COMMIT(); }

    float rAcc[4][2];
#pragma unroll
    for (int mi = 0; mi < 4; ++mi) { rAcc[mi][0] = 0.f; rAcc[mi][1] = 0.f; }

    float acc[4][4][4];
#pragma unroll
    for (int mi = 0; mi < 4; ++mi)
#pragma unroll
        for (int ni = 0; ni < 4; ++ni)
#pragma unroll
            for (int j = 0; j < 4; ++j) acc[mi][ni][j] = 0.0f;

    for (int g = 0; g < NSTAGES; ++g) {
        CP_WAIT2();
        __syncthreads();
        if (g + 3 < NSTAGES) issue_stage(g + 3);
        CP_COMMIT();

        const uint32_t bufOff = (g & 3) * CLS_B_TILE;
        const uint32_t aOff = (g & 7) * 32;   // 32 fp8 = 32B per k step
        uint32_t a[4][4], bb[2][4];
#pragma unroll
        for (int mi = 0; mi < 4; ++mi)
            ldsm_x4(a[mi], aBase[mi] + aOff);
#pragma unroll
        for (int ng = 0; ng < 2; ++ng)
            ldsm_x4(bb[ng], bBase[ng] + bufOff);
#pragma unroll
        for (int mi = 0; mi < 4; ++mi)
#pragma unroll
            for (int ni = 0; ni < 4; ++ni)
                mma_fp8(acc[mi][ni], a[mi],
                        bb[ni >> 1][(ni & 1) * 2],
                        bb[ni >> 1][(ni & 1) * 2 + 1]);

        if ((g & 7) == 7) {
            const int v0 = v_base + (g >> 3) * CLS_BN;
            const float* bop = bo + v0 + wn * 32 + (lane & 3) * 2;
#pragma unroll
            for (int ni = 0; ni < 4; ++ni) {
                float2 bv = *(const float2*)(bop + ni * 8);
                float b0 = bv.x * LOG2E, b1 = bv.y * LOG2E;
#pragma unroll
                for (int mi = 0; mi < 4; ++mi) {
                    rAcc[mi][0] += ex2f(fmaf(acc[mi][ni][0], K2, b0))
                                 + ex2f(fmaf(acc[mi][ni][1], K2, b1));
                    rAcc[mi][1] += ex2f(fmaf(acc[mi][ni][2], K2, b0))
                                 + ex2f(fmaf(acc[mi][ni][3], K2, b1));
                    acc[mi][ni][0] = 0.f; acc[mi][ni][1] = 0.f;
                    acc[mi][ni][2] = 0.f; acc[mi][ni][3] = 0.f;
                }
            }
        }
    }
    CP_WAITALL();

#pragma unroll
    for (int mi = 0; mi < 4; ++mi)
#pragma unroll
        for (int hi = 0; hi < 2; ++hi) {
            float v = rAcc[mi][hi];
            v += __shfl_xor_sync(0xFFFFFFFFu, v, 1);
            v += __shfl_xor_sync(0xFFFFFFFFu, v, 2);
            if ((lane & 3) == 0)
                atomicAdd(&red[wm * 64 + mi * 16 + hi * 8 + (lane >> 2)], v);
        }
    __syncthreads();
    if (tid < 128)
        g_partial[(size_t)(l0 + tid) * NSPLIT + blockIdx.y] = red[tid];
}

// ---------------------------------------------------------------------------
__global__ void zero_kernel(float* out) { out[0] = 0.0f; }

// ---------------------------------------------------------------------------
// loss: per-row fp32 tag logit + log(sum partials) + global sum
// ---------------------------------------------------------------------------
__global__ void loss_kernel(const float* __restrict__ Wo,
                            const float* __restrict__ bo,
                            const int* __restrict__ tags,
                            float* __restrict__ out) {
    const int warp = (blockIdx.x * blockDim.x + threadIdx.x) >> 5;
    const int lane = threadIdx.x & 31;
    const int nwarps = (gridDim.x * blockDim.x) >> 5;
    float local = 0.0f;
    for (int l = warp; l < L_; l += nwarps) {
        int tag = tags[l];
        float dot = 0.0f;
#pragma unroll
        for (int j = 0; j < 8; ++j) {
            int k = lane + j * 32;
            dot += g_feat[(size_t)l * 256 + k] * Wo[(size_t)k * V_ + tag];
        }
#pragma unroll
        for (int off = 16; off > 0; off >>= 1)
            dot += __shfl_down_sync(0xFFFFFFFFu, dot, off);
        if (lane == 0) {
            float s = 0.0f;
#pragma unroll
            for (int sp = 0; sp < NSPLIT; ++sp)
                s += g_partial[(size_t)l * NSPLIT + sp];
            local += logf(s) - (dot + bo[tag]);
        }
    }
    if (lane == 0)
        atomicAdd(out, local * (1.0f / (4096.0f + 1e-5f)));
}

// ---------------------------------------------------------------------------
// Launch. Inputs: hidden, begins, ends, bids, tags, W1, b1, W2, b2, Wo, bo
// ---------------------------------------------------------------------------
extern "C" void kernel_launch(void* const* d_in, const int* in_sizes, int n_in,
                              void* d_out, int out_size) {
    const float* hidden = (const float*)d_in[0];
    const int*   begins = (const int*)d_in[1];
    const int*   ends   = (const int*)d_in[2];
    const int*   bids   = (const int*)d_in[3];
    const int*   tags   = (const int*)d_in[4];
    const float* W1     = (const float*)d_in[5];
    const float* b1     = (const float*)d_in[6];
    const float* W2     = (const float*)d_in[7];
    const float* b2     = (const float*)d_in[8];
    const float* Wo     = (const float*)d_in[9];
    const float* bo     = (const float*)d_in[10];
    float* out = (float*)d_out;

    __nv_bfloat16 *spanb, *h1b, *w1b, *w2b;
    float* feat;
    uint8_t* wot8;
    cudaGetSymbolAddress((void**)&spanb, g_spanb);
    cudaGetSymbolAddress((void**)&h1b, g_h1b);
    cudaGetSymbolAddress((void**)&feat, g_feat);
    cudaGetSymbolAddress((void**)&w1b, g_w1b);
    cudaGetSymbolAddress((void**)&w2b, g_w2b);
    cudaGetSymbolAddress((void**)&wot8, g_wot8);

    // weight prep
    cvt_kernel<<<(3 * H_ * LAB_ / 4 + 255) / 256, 256>>>(W1, w1b, 3 * H_ * LAB_ / 4);
    cvt_kernel<<<(LAB_ * LAB_ / 4 + 255) / 256, 256>>>(W2, w2b, LAB_ * LAB_ / 4);
    {
        dim3 grid(V_ / 32, LAB_ / 32);
        wo8_kernel<<<grid, dim3(32, 8)>>>(Wo, wot8);
    }

    // 1) span embeddings (bf16)
    span_kernel<<<L_, 128>>>(hidden, begins, ends, bids);

    // 2) h1 = sigmoid(span @ W1 + b1) -> bf16
    {
        dim3 grid(L_ / 128, LAB_ / 64);
        wgemm_kernel<3 * H_, 1><<<grid, 256, WG_SMEM_BYTES>>>(
            spanb, w1b, b1, nullptr, h1b, LAB_);
    }
    // 3) feat = h1 @ W2 + b2 -> fp32 + e4m3
    {
        dim3 grid(L_ / 128, LAB_ / 64);
        wgemm_kernel<LAB_, 2><<<grid, 256, WG_SMEM_BYTES>>>(
            h1b, w2b, b2, feat, nullptr, LAB_);
    }
    // 4) fp8 mma.sync classifier GEMM + fused exp-sum partials
    {
        cudaFuncSetAttribute(cls_kernel,
                             cudaFuncAttributeMaxDynamicSharedMemorySize,
                             CLS_SMEM);
        dim3 grid(L_ / CLS_BM, NSPLIT);
        cls_kernel<<<grid, 256, CLS_SMEM>>>(bo);
    }
    // 5) final loss reduction
    zero_kernel<<<1, 1>>>(out);
    loss_kernel<<<32, 256>>>(Wo, bo, tags, out);
}

// round 8
// speedup vs baseline: 1.2318x; 1.2318x over previous
#include <cuda_runtime.h>
#include <cuda_bf16.h>
#include <mma.h>
#include <math.h>
#include <stdint.h>

using namespace nvcuda;

// Problem constants
#define S_    2048
#define B_    16
#define H_    512
#define L_    4096
#define LAB_  256
#define V_    32000

// cls tiling
#define CLS_BM   128
#define CLS_BN   128
#define CLS_VT   10              // 64-col... 128-col tiles per CTA
#define NSPLIT   25              // 25 * 10 * 128 = 32000
#define VCHUNK   (CLS_VT * CLS_BN)   // 1280
#define NSTAGES  (CLS_VT * 8)    // 80 stages of K=32

// cls smem (bytes)
#define AS_LDB   528             // A row stride bytes (264 bf16)
#define BS_LDB   272             // B row stride bytes (136 bf16)
#define CLS_A_OFF 0
#define CLS_A_BYTES (CLS_BM * AS_LDB)        // 67584
#define CLS_B_OFF  CLS_A_BYTES
#define CLS_B_TILE (32 * BS_LDB)             // 8704 (K=32 x 128 cols)
#define CLS_B_BYTES (4 * CLS_B_TILE)         // 34816 (4-stage ring)
#define CLS_RED_OFF (CLS_B_OFF + CLS_B_BYTES)
#define CLS_SMEM (CLS_RED_OFF + 128 * 4)     // 102912 -> 2 CTAs/SM

// wgemm smem
#define CS_LD 68
#define WG_AS_BYTES (128 * 72 * 2)
#define WG_BS_OFF   WG_AS_BYTES
#define WG_SMEM_BYTES 35840

// Scratch (static device globals)
__device__ __nv_bfloat16 g_spanb[(size_t)L_ * 3 * H_];
__device__ __nv_bfloat16 g_h1b[(size_t)L_ * LAB_];
__device__ float g_feat[(size_t)L_ * LAB_];
__device__ __nv_bfloat16 g_featb[(size_t)L_ * LAB_];
__device__ __nv_bfloat16 g_w1b[(size_t)3 * H_ * LAB_];
__device__ __nv_bfloat16 g_w2b[(size_t)LAB_ * LAB_];
__device__ __nv_bfloat16 g_wob[(size_t)LAB_ * V_];      // Wo bf16 [256][32000]
__device__ float g_partial[(size_t)L_ * NSPLIT];

// ---------------------------------------------------------------------------
// PTX primitives (sm80-baseline)
// ---------------------------------------------------------------------------
__device__ __forceinline__ uint32_t smem_u32(const void* p) {
    uint32_t a;
    asm("{ .reg .u64 t; cvta.to.shared.u64 t, %1; cvt.u32.u64 %0, t; }"
        : "=r"(a) : "l"(p));
    return a;
}
__device__ __forceinline__ void ldsm_x4(uint32_t r[4], uint32_t addr) {
    asm volatile("ldmatrix.sync.aligned.m8n8.x4.shared.b16 {%0,%1,%2,%3}, [%4];"
        : "=r"(r[0]), "=r"(r[1]), "=r"(r[2]), "=r"(r[3]) : "r"(addr));
}
__device__ __forceinline__ void ldsm_x4_t(uint32_t r[4], uint32_t addr) {
    asm volatile("ldmatrix.sync.aligned.m8n8.x4.trans.shared.b16 {%0,%1,%2,%3}, [%4];"
        : "=r"(r[0]), "=r"(r[1]), "=r"(r[2]), "=r"(r[3]) : "r"(addr));
}
__device__ __forceinline__ void mma_bf16(float d[4], const uint32_t a[4],
                                         uint32_t b0, uint32_t b1) {
    asm volatile(
        "mma.sync.aligned.m16n8k16.row.col.f32.bf16.bf16.f32 "
        "{%0,%1,%2,%3}, {%4,%5,%6,%7}, {%8,%9}, {%0,%1,%2,%3};"
        : "+f"(d[0]), "+f"(d[1]), "+f"(d[2]), "+f"(d[3])
        : "r"(a[0]), "r"(a[1]), "r"(a[2]), "r"(a[3]), "r"(b0), "r"(b1));
}
#define CP_ASYNC16(dst, src) \
    asm volatile("cp.async.cg.shared.global [%0], [%1], 16;" \
        :: "r"(dst), "l"(src) : "memory")
#define CP_COMMIT() asm volatile("cp.async.commit_group;" ::: "memory")
#define CP_WAIT2()  asm volatile("cp.async.wait_group 2;" ::: "memory")
#define CP_WAITALL() asm volatile("cp.async.wait_group 0;" ::: "memory")

__device__ __forceinline__ float ex2f(float x) {
    float r;
    asm("ex2.approx.f32 %0, %1;" : "=f"(r) : "f"(x));
    return r;
}

// ---------------------------------------------------------------------------
// fast exp poly (sigmoid epilogue in wgemm)
// ---------------------------------------------------------------------------
__device__ __forceinline__ float fast_exp(float x) {
    float z = x * 1.4426950408889634f;
    float r = rintf(z);
    float f = z - r;
    float p = 1.3333558146428443e-3f;
    p = fmaf(p, f, 9.6181291976036120e-3f);
    p = fmaf(p, f, 5.5504108664821580e-2f);
    p = fmaf(p, f, 2.4022650695910072e-1f);
    p = fmaf(p, f, 6.9314718055994531e-1f);
    p = fmaf(p, f, 1.0f);
    return __int_as_float(((int)r + 127) << 23) * p;
}

// ---------------------------------------------------------------------------
// span embeddings -> bf16 (float4 vectorized, 128 threads)
// ---------------------------------------------------------------------------
__global__ void span_kernel(const float* __restrict__ hidden,
                            const int* __restrict__ begins,
                            const int* __restrict__ ends,
                            const int* __restrict__ bids) {
    const int l = blockIdx.x;
    const int beg = begins[l];
    const int end = ends[l];
    const int b   = bids[l];
    const float inv_len = 1.0f / (float)(end - beg);
    const float4* hp = (const float4*)hidden;
    const int h4 = threadIdx.x;            // 0..127
    const int H4 = H_ / 4;

    float4 left  = hp[((size_t)(beg - 1) * B_ + b) * H4 + h4];
    float4 right = hp[((size_t)end * B_ + b) * H4 + h4];
    float4 s = make_float4(0.f, 0.f, 0.f, 0.f);
    for (int t = beg; t < end; ++t) {
        float4 v = hp[((size_t)t * B_ + b) * H4 + h4];
        s.x += v.x; s.y += v.y; s.z += v.z; s.w += v.w;
    }
    __nv_bfloat16* out = g_spanb + (size_t)l * (3 * H_);
    uint2 pk;
    pk.x = __nv_bfloat162_raw(__floats2bfloat162_rn(left.x, left.y)).x;
    pk.y = __nv_bfloat162_raw(__floats2bfloat162_rn(left.z, left.w)).x;
    *(uint2*)&out[h4 * 4] = pk;
    pk.x = __nv_bfloat162_raw(__floats2bfloat162_rn(s.x * inv_len, s.y * inv_len)).x;
    pk.y = __nv_bfloat162_raw(__floats2bfloat162_rn(s.z * inv_len, s.w * inv_len)).x;
    *(uint2*)&out[H_ + h4 * 4] = pk;
    pk.x = __nv_bfloat162_raw(__floats2bfloat162_rn(right.x, right.y)).x;
    pk.y = __nv_bfloat162_raw(__floats2bfloat162_rn(right.z, right.w)).x;
    *(uint2*)&out[2 * H_ + h4 * 4] = pk;
}

// ---------------------------------------------------------------------------
// fp32 -> bf16 conversion
// ---------------------------------------------------------------------------
__global__ void cvt_kernel(const float* __restrict__ src,
                           __nv_bfloat16* __restrict__ dst, int n4) {
    int i = blockIdx.x * blockDim.x + threadIdx.x;
    if (i < n4) {
        float4 v = ((const float4*)src)[i];
        ((__nv_bfloat162*)dst)[2 * i]     = __floats2bfloat162_rn(v.x, v.y);
        ((__nv_bfloat162*)dst)[2 * i + 1] = __floats2bfloat162_rn(v.z, v.w);
    }
}

// ---------------------------------------------------------------------------
// bf16 wmma GEMM for GEMM1/GEMM2
// ---------------------------------------------------------------------------
template<int K, int EPI>
__global__ __launch_bounds__(256)
void wgemm_kernel(const __nv_bfloat16* __restrict__ A,
                  const __nv_bfloat16* __restrict__ B,
                  const float* __restrict__ bias,
                  float* __restrict__ C32,
                  __nv_bfloat16* __restrict__ Cb, int N) {
    extern __shared__ char smem[];
    __nv_bfloat16* As = (__nv_bfloat16*)smem;
    __nv_bfloat16* Bs = (__nv_bfloat16*)(smem + WG_BS_OFF);
    float* Cs = (float*)smem;

    const int tid = threadIdx.x;
    const int wid = tid >> 5;
    const int lane = tid & 31;
    const int m0 = blockIdx.x * 128;
    const int n0 = blockIdx.y * 64;

    wmma::fragment<wmma::accumulator, 16, 16, 16, float> acc[4];
#pragma unroll
    for (int j = 0; j < 4; ++j) wmma::fill_fragment(acc[j], 0.0f);

    for (int k0 = 0; k0 < K; k0 += 64) {
        __syncthreads();
#pragma unroll
        for (int t = tid; t < 128 * 8; t += 256) {
            int m = t >> 3, k8 = t & 7;
            uint4 v = *(const uint4*)&A[(size_t)(m0 + m) * K + k0 + k8 * 8];
            *(uint4*)&As[m * 72 + k8 * 8] = v;
        }
#pragma unroll
        for (int t = tid; t < 64 * 8; t += 256) {
            int k = t >> 3, n8 = t & 7;
            uint4 v = *(const uint4*)&B[(size_t)(k0 + k) * N + n0 + n8 * 8];
            *(uint4*)&Bs[k * 72 + n8 * 8] = v;
        }
        __syncthreads();
#pragma unroll
        for (int ks = 0; ks < 4; ++ks) {
            wmma::fragment<wmma::matrix_a, 16, 16, 16, __nv_bfloat16, wmma::row_major> af;
            wmma::load_matrix_sync(af, &As[(wid * 16) * 72 + ks * 16], 72);
#pragma unroll
            for (int nt = 0; nt < 4; ++nt) {
                wmma::fragment<wmma::matrix_b, 16, 16, 16, __nv_bfloat16, wmma::row_major> bf;
                wmma::load_matrix_sync(bf, &Bs[(ks * 16) * 72 + nt * 16], 72);
                wmma::mma_sync(acc[nt], af, bf, acc[nt]);
            }
        }
    }
    __syncthreads();

    float* Cw = Cs + wid * 16 * CS_LD;
#pragma unroll
    for (int nt = 0; nt < 4; ++nt)
        wmma::store_matrix_sync(&Cw[nt * 16], acc[nt], CS_LD, wmma::mem_row_major);
    __syncwarp();

#pragma unroll
    for (int e = 0; e < 32; ++e) {
        int idx = lane + e * 32;
        int r = idx >> 6, c = idx & 63;
        int gr = m0 + wid * 16 + r;
        int gc = n0 + c;
        float v = Cw[r * CS_LD + c] + bias[gc];
        if (EPI == 1) {
            v = 1.0f / (1.0f + fast_exp(-v));
            Cb[(size_t)gr * N + gc] = __float2bfloat16(v);
        } else {
            C32[(size_t)gr * N + gc] = v;
            Cb[(size_t)gr * N + gc] = __float2bfloat16(v);
        }
    }
}

// ---------------------------------------------------------------------------
// cls: raw mma.sync bf16 classifier GEMM + fused per-row exp-sums.
// 4-stage cp.async ring, K=32 per stage, 80 stages (VT=10 tiles of 128 cols).
// 8 warps: wm = wid>>2 (2 row groups of 64), wn = wid&3 (4 col groups of 32).
// grid (L/128 = 32, NSPLIT = 25) = 800 CTAs -> fine-grained waves.
// ---------------------------------------------------------------------------
__global__ __launch_bounds__(256, 2)
void cls_kernel(const float* __restrict__ bo) {
    extern __shared__ char smem[];
    const uint32_t sb = smem_u32(smem);
    float* red = (float*)(smem + CLS_RED_OFF);

    const int tid = threadIdx.x;
    const int wid = tid >> 5;
    const int lane = tid & 31;
    const int wm = wid >> 2;          // 0..1
    const int wn = wid & 3;           // 0..3
    const int l0 = blockIdx.x * CLS_BM;
    const int v_base = blockIdx.y * VCHUNK;
    const float LOG2E = 1.4426950408889634f;

    // Stage A: 128 rows x 256 bf16, padded rows
    {
        const __nv_bfloat16* src = g_featb + (size_t)l0 * LAB_;
#pragma unroll
        for (int t = tid; t < 128 * 32; t += 256) {
            int r = t >> 5, k8 = t & 31;
            uint4 v = *(const uint4*)&src[(size_t)r * LAB_ + k8 * 8];
            *(uint4*)(smem + CLS_A_OFF + r * AS_LDB + k8 * 16) = v;
        }
    }
    if (tid < 128) red[tid] = 0.0f;

    // per-thread B cp.async components: 512 chunks of 16B per stage, 2/thread
    const int c0row = tid >> 4, c0col = tid & 15;
    const int c1row = (tid + 256) >> 4, c1col = (tid + 256) & 15;

    // A ldmatrix base addresses (per m-frag)
    uint32_t aBase[4];
#pragma unroll
    for (int mi = 0; mi < 4; ++mi)
        aBase[mi] = sb + CLS_A_OFF
                  + (wm * 64 + mi * 16 + (lane & 15)) * AS_LDB
                  + (lane >> 4) * 16;
    // B ldmatrix base (per 16-col group)
    uint32_t bBase[2];
#pragma unroll
    for (int ng = 0; ng < 2; ++ng)
        bBase[ng] = sb + CLS_B_OFF + (lane & 15) * BS_LDB
                  + (wn * 32 + ng * 16) * 2 + (lane >> 4) * 16;

    auto issue_stage = [&](int st) {
        const int k0 = (st & 7) * 32;
        const int v0 = v_base + (st >> 3) * CLS_BN;
        const uint32_t dbase = sb + CLS_B_OFF + (st & 3) * CLS_B_TILE;
        const __nv_bfloat16* s0 =
            g_wob + (size_t)(k0 + c0row) * V_ + v0 + c0col * 8;
        const __nv_bfloat16* s1 =
            g_wob + (size_t)(k0 + c1row) * V_ + v0 + c1col * 8;
        CP_ASYNC16(dbase + c0row * BS_LDB + c0col * 16, (const char*)s0);
        CP_ASYNC16(dbase + c1row * BS_LDB + c1col * 16, (const char*)s1);
    };

#pragma unroll
    for (int st = 0; st < 3; ++st) { issue_stage(st); CP_COMMIT(); }

    float rAcc[4][2];
#pragma unroll
    for (int mi = 0; mi < 4; ++mi) { rAcc[mi][0] = 0.f; rAcc[mi][1] = 0.f; }

    float acc[4][4][4];
#pragma unroll
    for (int mi = 0; mi < 4; ++mi)
#pragma unroll
        for (int ni = 0; ni < 4; ++ni)
#pragma unroll
            for (int j = 0; j < 4; ++j) acc[mi][ni][j] = 0.0f;

    for (int g = 0; g < NSTAGES; ++g) {
        CP_WAIT2();
        __syncthreads();
        if (g + 3 < NSTAGES) issue_stage(g + 3);
        CP_COMMIT();   // always commit (empty groups keep count exact)

        const uint32_t bufOff = (g & 3) * CLS_B_TILE;
        const uint32_t aOff = (g & 7) * 64;
#pragma unroll
        for (int s = 0; s < 2; ++s) {
            uint32_t a[4][4], bb[2][4];
#pragma unroll
            for (int mi = 0; mi < 4; ++mi)
                ldsm_x4(a[mi], aBase[mi] + aOff + s * 32);
#pragma unroll
            for (int ng = 0; ng < 2; ++ng)
                ldsm_x4_t(bb[ng], bBase[ng] + bufOff + s * 16 * BS_LDB);
#pragma unroll
            for (int mi = 0; mi < 4; ++mi)
#pragma unroll
                for (int ni = 0; ni < 4; ++ni)
                    mma_bf16(acc[mi][ni], a[mi],
                             bb[ni >> 1][(ni & 1) * 2],
                             bb[ni >> 1][(ni & 1) * 2 + 1]);
        }

        if ((g & 7) == 7) {
            const int v0 = v_base + (g >> 3) * CLS_BN;
            const float* bop = bo + v0 + wn * 32 + (lane & 3) * 2;
#pragma unroll
            for (int ni = 0; ni < 4; ++ni) {
                float2 bv = *(const float2*)(bop + ni * 8);
                float b0 = bv.x * LOG2E, b1 = bv.y * LOG2E;
#pragma unroll
                for (int mi = 0; mi < 4; ++mi) {
                    rAcc[mi][0] += ex2f(fmaf(acc[mi][ni][0], LOG2E, b0))
                                 + ex2f(fmaf(acc[mi][ni][1], LOG2E, b1));
                    rAcc[mi][1] += ex2f(fmaf(acc[mi][ni][2], LOG2E, b0))
                                 + ex2f(fmaf(acc[mi][ni][3], LOG2E, b1));
                    acc[mi][ni][0] = 0.f; acc[mi][ni][1] = 0.f;
                    acc[mi][ni][2] = 0.f; acc[mi][ni][3] = 0.f;
                }
            }
        }
    }
    CP_WAITALL();

    // reduce quads (columns) then across wn warps via smem atomics
#pragma unroll
    for (int mi = 0; mi < 4; ++mi)
#pragma unroll
        for (int hi = 0; hi < 2; ++hi) {
            float v = rAcc[mi][hi];
            v += __shfl_xor_sync(0xFFFFFFFFu, v, 1);
            v += __shfl_xor_sync(0xFFFFFFFFu, v, 2);
            if ((lane & 3) == 0)
                atomicAdd(&red[wm * 64 + mi * 16 + hi * 8 + (lane >> 2)], v);
        }
    __syncthreads();
    if (tid < 128)
        g_partial[(size_t)(l0 + tid) * NSPLIT + blockIdx.y] = red[tid];
}

// ---------------------------------------------------------------------------
__global__ void zero_kernel(float* out) { out[0] = 0.0f; }

// ---------------------------------------------------------------------------
// loss: per-row fp32 tag logit + log(sum partials) + global sum
// ---------------------------------------------------------------------------
__global__ void loss_kernel(const float* __restrict__ Wo,
                            const float* __restrict__ bo,
                            const int* __restrict__ tags,
                            float* __restrict__ out) {
    const int warp = (blockIdx.x * blockDim.x + threadIdx.x) >> 5;
    const int lane = threadIdx.x & 31;
    const int nwarps = (gridDim.x * blockDim.x) >> 5;
    float local = 0.0f;
    for (int l = warp; l < L_; l += nwarps) {
        int tag = tags[l];
        float dot = 0.0f;
#pragma unroll
        for (int j = 0; j < 8; ++j) {
            int k = lane + j * 32;
            dot += g_feat[(size_t)l * 256 + k] * Wo[(size_t)k * V_ + tag];
        }
#pragma unroll
        for (int off = 16; off > 0; off >>= 1)
            dot += __shfl_down_sync(0xFFFFFFFFu, dot, off);
        if (lane == 0) {
            float s = 0.0f;
#pragma unroll
            for (int sp = 0; sp < NSPLIT; ++sp)
                s += g_partial[(size_t)l * NSPLIT + sp];
            local += logf(s) - (dot + bo[tag]);
        }
    }
    if (lane == 0)
        atomicAdd(out, local * (1.0f / (4096.0f + 1e-5f)));
}

// ---------------------------------------------------------------------------
// Launch. Inputs: hidden, begins, ends, bids, tags, W1, b1, W2, b2, Wo, bo
// ---------------------------------------------------------------------------
extern "C" void kernel_launch(void* const* d_in, const int* in_sizes, int n_in,
                              void* d_out, int out_size) {
    const float* hidden = (const float*)d_in[0];
    const int*   begins = (const int*)d_in[1];
    const int*   ends   = (const int*)d_in[2];
    const int*   bids   = (const int*)d_in[3];
    const int*   tags   = (const int*)d_in[4];
    const float* W1     = (const float*)d_in[5];
    const float* b1     = (const float*)d_in[6];
    const float* W2     = (const float*)d_in[7];
    const float* b2     = (const float*)d_in[8];
    const float* Wo     = (const float*)d_in[9];
    const float* bo     = (const float*)d_in[10];
    float* out = (float*)d_out;

    __nv_bfloat16 *spanb, *h1b, *featb, *w1b, *w2b, *wob;
    float* feat;
    cudaGetSymbolAddress((void**)&spanb, g_spanb);
    cudaGetSymbolAddress((void**)&h1b, g_h1b);
    cudaGetSymbolAddress((void**)&feat, g_feat);
    cudaGetSymbolAddress((void**)&featb, g_featb);
    cudaGetSymbolAddress((void**)&w1b, g_w1b);
    cudaGetSymbolAddress((void**)&w2b, g_w2b);
    cudaGetSymbolAddress((void**)&wob, g_wob);

    // weight prep (bf16)
    cvt_kernel<<<(3 * H_ * LAB_ / 4 + 255) / 256, 256>>>(W1, w1b, 3 * H_ * LAB_ / 4);
    cvt_kernel<<<(LAB_ * LAB_ / 4 + 255) / 256, 256>>>(W2, w2b, LAB_ * LAB_ / 4);
    cvt_kernel<<<(LAB_ * V_ / 4 + 255) / 256, 256>>>(Wo, wob, LAB_ * V_ / 4);

    // 1) span embeddings (bf16)
    span_kernel<<<L_, 128>>>(hidden, begins, ends, bids);

    // 2) h1 = sigmoid(span @ W1 + b1) -> bf16
    {
        dim3 grid(L_ / 128, LAB_ / 64);
        wgemm_kernel<3 * H_, 1><<<grid, 256, WG_SMEM_BYTES>>>(
            spanb, w1b, b1, nullptr, h1b, LAB_);
    }
    // 3) feat = h1 @ W2 + b2 -> fp32 + bf16
    {
        dim3 grid(L_ / 128, LAB_ / 64);
        wgemm_kernel<LAB_, 2><<<grid, 256, WG_SMEM_BYTES>>>(
            h1b, w2b, b2, feat, featb, LAB_);
    }
    // 4) mma.sync classifier GEMM + fused exp-sum partials
    {
        cudaFuncSetAttribute(cls_kernel,
                             cudaFuncAttributeMaxDynamicSharedMemorySize,
                             CLS_SMEM);
        dim3 grid(L_ / CLS_BM, NSPLIT);
        cls_kernel<<<grid, 256, CLS_SMEM>>>(bo);
    }
    // 5) final loss reduction
    zero_kernel<<<1, 1>>>(out);
    loss_kernel<<<32, 256>>>(Wo, bo, tags, out);
}

// round 10
// speedup vs baseline: 1.2549x; 1.0188x over previous
#include <cuda_runtime.h>
#include <cuda_bf16.h>
#include <mma.h>
#include <math.h>
#include <stdint.h>

using namespace nvcuda;

// Problem constants
#define S_    2048
#define B_    16
#define H_    512
#define L_    4096
#define LAB_  256
#define V_    32000

// cls tiling
#define CLS_BM   128
#define CLS_BN   128
#define CLS_VT   2               // 128-col tiles per CTA
#define NSPLIT   125             // 125 * 2 * 128 = 32000
#define VCHUNK   (CLS_VT * CLS_BN)   // 256
#define NSTAGES  (CLS_VT * 8)    // 16 stages of K=32

// cls smem (bytes)
#define AS_LDB   528             // A row stride bytes (264 bf16)
#define BS_LDB   272             // B row stride bytes (136 bf16)
#define CLS_A_OFF 0
#define CLS_A_BYTES (CLS_BM * AS_LDB)        // 67584
#define CLS_B_OFF  CLS_A_BYTES
#define CLS_B_TILE (32 * BS_LDB)             // 8704
#define CLS_B_BYTES (4 * CLS_B_TILE)         // 34816 (4-stage ring)
#define CLS_RED_OFF (CLS_B_OFF + CLS_B_BYTES)
#define CLS_SMEM (CLS_RED_OFF + 128 * 4)     // 102912 -> 2 CTAs/SM

// wgemm smem (2-stage cp.async pipeline)
#define CS_LD 68
#define WG_A_BUF (128 * 144)                 // 18432 per buf
#define WG_B_BUF (64 * 144)                  // 9216 per buf
#define WG_B_OFF (2 * WG_A_BUF)              // 36864
#define WG_SMEM_BYTES (WG_B_OFF + 2 * WG_B_BUF)  // 55296 (>= Cs 34816)

// Scratch (static device globals)
__device__ __nv_bfloat16 g_spanb[(size_t)L_ * 3 * H_];
__device__ __nv_bfloat16 g_h1b[(size_t)L_ * LAB_];
__device__ float g_feat[(size_t)L_ * LAB_];
__device__ __nv_bfloat16 g_featb[(size_t)L_ * LAB_];
__device__ __nv_bfloat16 g_w1b[(size_t)3 * H_ * LAB_];
__device__ __nv_bfloat16 g_w2b[(size_t)LAB_ * LAB_];
__device__ __nv_bfloat16 g_wob[(size_t)LAB_ * V_];      // Wo bf16 [256][32000]
__device__ float g_partial[(size_t)L_ * NSPLIT];

// ---------------------------------------------------------------------------
// PTX primitives (sm80-baseline)
// ---------------------------------------------------------------------------
__device__ __forceinline__ uint32_t smem_u32(const void* p) {
    uint32_t a;
    asm("{ .reg .u64 t; cvta.to.shared.u64 t, %1; cvt.u32.u64 %0, t; }"
        : "=r"(a) : "l"(p));
    return a;
}
__device__ __forceinline__ void ldsm_x4(uint32_t r[4], uint32_t addr) {
    asm volatile("ldmatrix.sync.aligned.m8n8.x4.shared.b16 {%0,%1,%2,%3}, [%4];"
        : "=r"(r[0]), "=r"(r[1]), "=r"(r[2]), "=r"(r[3]) : "r"(addr));
}
__device__ __forceinline__ void ldsm_x4_t(uint32_t r[4], uint32_t addr) {
    asm volatile("ldmatrix.sync.aligned.m8n8.x4.trans.shared.b16 {%0,%1,%2,%3}, [%4];"
        : "=r"(r[0]), "=r"(r[1]), "=r"(r[2]), "=r"(r[3]) : "r"(addr));
}
__device__ __forceinline__ void mma_bf16(float d[4], const uint32_t a[4],
                                         uint32_t b0, uint32_t b1) {
    asm volatile(
        "mma.sync.aligned.m16n8k16.row.col.f32.bf16.bf16.f32 "
        "{%0,%1,%2,%3}, {%4,%5,%6,%7}, {%8,%9}, {%0,%1,%2,%3};"
        : "+f"(d[0]), "+f"(d[1]), "+f"(d[2]), "+f"(d[3])
        : "r"(a[0]), "r"(a[1]), "r"(a[2]), "r"(a[3]), "r"(b0), "r"(b1));
}
#define CP_ASYNC16(dst, src) \
    asm volatile("cp.async.cg.shared.global [%0], [%1], 16;" \
        :: "r"(dst), "l"(src) : "memory")
#define CP_COMMIT() asm volatile("cp.async.commit_group;" ::: "memory")
#define CP_WAIT1()  asm volatile("cp.async.wait_group 1;" ::: "memory")
#define CP_WAIT2()  asm volatile("cp.async.wait_group 2;" ::: "memory")
#define CP_WAITALL() asm volatile("cp.async.wait_group 0;" ::: "memory")

__device__ __forceinline__ float ex2f(float x) {
    float r;
    asm("ex2.approx.f32 %0, %1;" : "=f"(r) : "f"(x));
    return r;
}

// ---------------------------------------------------------------------------
// fast exp poly (sigmoid epilogue in wgemm)
// ---------------------------------------------------------------------------
__device__ __forceinline__ float fast_exp(float x) {
    float z = x * 1.4426950408889634f;
    float r = rintf(z);
    float f = z - r;
    float p = 1.3333558146428443e-3f;
    p = fmaf(p, f, 9.6181291976036120e-3f);
    p = fmaf(p, f, 5.5504108664821580e-2f);
    p = fmaf(p, f, 2.4022650695910072e-1f);
    p = fmaf(p, f, 6.9314718055994531e-1f);
    p = fmaf(p, f, 1.0f);
    return __int_as_float(((int)r + 127) << 23) * p;
}

// ---------------------------------------------------------------------------
// span embeddings -> bf16 (float4, 2-way unrolled gather for MLP)
// ---------------------------------------------------------------------------
__global__ void span_kernel(const float* __restrict__ hidden,
                            const int* __restrict__ begins,
                            const int* __restrict__ ends,
                            const int* __restrict__ bids) {
    const int l = blockIdx.x;
    const int beg = begins[l];
    const int end = ends[l];
    const int b   = bids[l];
    const float inv_len = 1.0f / (float)(end - beg);
    const float4* hp = (const float4*)hidden;
    const int h4 = threadIdx.x;            // 0..127
    const int H4 = H_ / 4;

    float4 left  = hp[((size_t)(beg - 1) * B_ + b) * H4 + h4];
    float4 right = hp[((size_t)end * B_ + b) * H4 + h4];
    float4 s0 = make_float4(0.f, 0.f, 0.f, 0.f);
    float4 s1 = make_float4(0.f, 0.f, 0.f, 0.f);
    int t = beg;
    for (; t + 2 <= end; t += 2) {
        float4 v0 = hp[((size_t)t * B_ + b) * H4 + h4];
        float4 v1 = hp[((size_t)(t + 1) * B_ + b) * H4 + h4];
        s0.x += v0.x; s0.y += v0.y; s0.z += v0.z; s0.w += v0.w;
        s1.x += v1.x; s1.y += v1.y; s1.z += v1.z; s1.w += v1.w;
    }
    if (t < end) {
        float4 v0 = hp[((size_t)t * B_ + b) * H4 + h4];
        s0.x += v0.x; s0.y += v0.y; s0.z += v0.z; s0.w += v0.w;
    }
    s0.x += s1.x; s0.y += s1.y; s0.z += s1.z; s0.w += s1.w;

    __nv_bfloat16* out = g_spanb + (size_t)l * (3 * H_);
    uint2 pk;
    pk.x = __nv_bfloat162_raw(__floats2bfloat162_rn(left.x, left.y)).x;
    pk.y = __nv_bfloat162_raw(__floats2bfloat162_rn(left.z, left.w)).x;
    *(uint2*)&out[h4 * 4] = pk;
    pk.x = __nv_bfloat162_raw(__floats2bfloat162_rn(s0.x * inv_len, s0.y * inv_len)).x;
    pk.y = __nv_bfloat162_raw(__floats2bfloat162_rn(s0.z * inv_len, s0.w * inv_len)).x;
    *(uint2*)&out[H_ + h4 * 4] = pk;
    pk.x = __nv_bfloat162_raw(__floats2bfloat162_rn(right.x, right.y)).x;
    pk.y = __nv_bfloat162_raw(__floats2bfloat162_rn(right.z, right.w)).x;
    *(uint2*)&out[2 * H_ + h4 * 4] = pk;
}

// ---------------------------------------------------------------------------
// prep: W1+W2 -> bf16, zero output scalar (fused launches)
// ---------------------------------------------------------------------------
#define N1_4 (3 * H_ * LAB_ / 4)
#define N2_4 (LAB_ * LAB_ / 4)
__global__ void prep_kernel(const float* __restrict__ W1,
                            const float* __restrict__ W2,
                            float* __restrict__ out) {
    int i = blockIdx.x * blockDim.x + threadIdx.x;
    if (i == 0) out[0] = 0.0f;
    if (i < N1_4) {
        float4 v = ((const float4*)W1)[i];
        ((__nv_bfloat162*)g_w1b)[2 * i]     = __floats2bfloat162_rn(v.x, v.y);
        ((__nv_bfloat162*)g_w1b)[2 * i + 1] = __floats2bfloat162_rn(v.z, v.w);
    } else if (i < N1_4 + N2_4) {
        int j = i - N1_4;
        float4 v = ((const float4*)W2)[j];
        ((__nv_bfloat162*)g_w2b)[2 * j]     = __floats2bfloat162_rn(v.x, v.y);
        ((__nv_bfloat162*)g_w2b)[2 * j + 1] = __floats2bfloat162_rn(v.z, v.w);
    }
}

// ---------------------------------------------------------------------------
// fp32 -> bf16 conversion (Wo)
// ---------------------------------------------------------------------------
__global__ void cvt_kernel(const float* __restrict__ src,
                           __nv_bfloat16* __restrict__ dst, int n4) {
    int i = blockIdx.x * blockDim.x + threadIdx.x;
    if (i < n4) {
        float4 v = ((const float4*)src)[i];
        ((__nv_bfloat162*)dst)[2 * i]     = __floats2bfloat162_rn(v.x, v.y);
        ((__nv_bfloat162*)dst)[2 * i + 1] = __floats2bfloat162_rn(v.z, v.w);
    }
}

// ---------------------------------------------------------------------------
// bf16 wmma GEMM for GEMM1/GEMM2, 2-stage cp.async pipeline.
// BM=128, BN=64, K per iter = 64. grid (M/128, N/64).
// ---------------------------------------------------------------------------
template<int K, int EPI>
__global__ __launch_bounds__(256)
void wgemm_kernel(const __nv_bfloat16* __restrict__ A,
                  const __nv_bfloat16* __restrict__ B,
                  const float* __restrict__ bias,
                  float* __restrict__ C32,
                  __nv_bfloat16* __restrict__ Cb, int N) {
    extern __shared__ char smem[];
    const uint32_t sb = smem_u32(smem);
    float* Cs = (float*)smem;   // epilogue alias

    const int tid = threadIdx.x;
    const int wid = tid >> 5;
    const int lane = tid & 31;
    const int m0 = blockIdx.x * 128;
    const int n0 = blockIdx.y * 64;
    constexpr int NIT = K / 64;

    auto issue = [&](int it) {
        const int k0 = it * 64;
        const int buf = it & 1;
        const uint32_t aDst = sb + buf * WG_A_BUF;
        const uint32_t bDst = sb + WG_B_OFF + buf * WG_B_BUF;
#pragma unroll
        for (int t = tid; t < 128 * 8; t += 256) {
            int m = t >> 3, k8 = t & 7;
            CP_ASYNC16(aDst + m * 144 + k8 * 16,
                       (const char*)&A[(size_t)(m0 + m) * K + k0 + k8 * 8]);
        }
#pragma unroll
        for (int t = tid; t < 64 * 8; t += 256) {
            int k = t >> 3, n8 = t & 7;
            CP_ASYNC16(bDst + k * 144 + n8 * 16,
                       (const char*)&B[(size_t)(k0 + k) * N + n0 + n8 * 8]);
        }
    };

    wmma::fragment<wmma::accumulator, 16, 16, 16, float> acc[4];
#pragma unroll
    for (int j = 0; j < 4; ++j) wmma::fill_fragment(acc[j], 0.0f);

    issue(0); CP_COMMIT();
    for (int it = 0; it < NIT; ++it) {
        if (it + 1 < NIT) { issue(it + 1); CP_COMMIT(); CP_WAIT1(); }
        else              { CP_WAITALL(); }
        __syncthreads();
        const int buf = it & 1;
        const __nv_bfloat16* As = (const __nv_bfloat16*)(smem + buf * WG_A_BUF);
        const __nv_bfloat16* Bs = (const __nv_bfloat16*)(smem + WG_B_OFF + buf * WG_B_BUF);
#pragma unroll
        for (int ks = 0; ks < 4; ++ks) {
            wmma::fragment<wmma::matrix_a, 16, 16, 16, __nv_bfloat16, wmma::row_major> af;
            wmma::load_matrix_sync(af, &As[(wid * 16) * 72 + ks * 16], 72);
#pragma unroll
            for (int nt = 0; nt < 4; ++nt) {
                wmma::fragment<wmma::matrix_b, 16, 16, 16, __nv_bfloat16, wmma::row_major> bf;
                wmma::load_matrix_sync(bf, &Bs[(ks * 16) * 72 + nt * 16], 72);
                wmma::mma_sync(acc[nt], af, bf, acc[nt]);
            }
        }
        __syncthreads();
    }

    float* Cw = Cs + wid * 16 * CS_LD;
#pragma unroll
    for (int nt = 0; nt < 4; ++nt)
        wmma::store_matrix_sync(&Cw[nt * 16], acc[nt], CS_LD, wmma::mem_row_major);
    __syncwarp();

#pragma unroll
    for (int e = 0; e < 32; ++e) {
        int idx = lane + e * 32;
        int r = idx >> 6, c = idx & 63;
        int gr = m0 + wid * 16 + r;
        int gc = n0 + c;
        float v = Cw[r * CS_LD + c] + bias[gc];
        if (EPI == 1) {
            v = 1.0f / (1.0f + fast_exp(-v));
            Cb[(size_t)gr * N + gc] = __float2bfloat16(v);
        } else {
            C32[(size_t)gr * N + gc] = v;
            Cb[(size_t)gr * N + gc] = __float2bfloat16(v);
        }
    }
}

// ---------------------------------------------------------------------------
// cls: raw mma.sync bf16 classifier GEMM + fused per-row exp-sums.
// 4-stage cp.async ring, K=32 per stage, 16 stages (VT=2 tiles of 128 cols).
// grid (32, 125) = 4000 CTAs -> 3.6% wave-quantization tail.
// ---------------------------------------------------------------------------
__global__ __launch_bounds__(256, 2)
void cls_kernel(const float* __restrict__ bo) {
    extern __shared__ char smem[];
    const uint32_t sb = smem_u32(smem);
    float* red = (float*)(smem + CLS_RED_OFF);

    const int tid = threadIdx.x;
    const int wid = tid >> 5;
    const int lane = tid & 31;
    const int wm = wid >> 2;
    const int wn = wid & 3;
    const int l0 = blockIdx.x * CLS_BM;
    const int v_base = blockIdx.y * VCHUNK;
    const float LOG2E = 1.4426950408889634f;

    // Stage A: 128 rows x 256 bf16
    {
        const __nv_bfloat16* src = g_featb + (size_t)l0 * LAB_;
#pragma unroll
        for (int t = tid; t < 128 * 32; t += 256) {
            int r = t >> 5, k8 = t & 31;
            uint4 v = *(const uint4*)&src[(size_t)r * LAB_ + k8 * 8];
            *(uint4*)(smem + CLS_A_OFF + r * AS_LDB + k8 * 16) = v;
        }
    }
    if (tid < 128) red[tid] = 0.0f;

    const int c0row = tid >> 4, c0col = tid & 15;
    const int c1row = (tid + 256) >> 4, c1col = (tid + 256) & 15;

    uint32_t aBase[4];
#pragma unroll
    for (int mi = 0; mi < 4; ++mi)
        aBase[mi] = sb + CLS_A_OFF
                  + (wm * 64 + mi * 16 + (lane & 15)) * AS_LDB
                  + (lane >> 4) * 16;
    uint32_t bBase[2];
#pragma unroll
    for (int ng = 0; ng < 2; ++ng)
        bBase[ng] = sb + CLS_B_OFF + (lane & 15) * BS_LDB
                  + (wn * 32 + ng * 16) * 2 + (lane >> 4) * 16;

    auto issue_stage = [&](int st) {
        const int k0 = (st & 7) * 32;
        const int v0 = v_base + (st >> 3) * CLS_BN;
        const uint32_t dbase = sb + CLS_B_OFF + (st & 3) * CLS_B_TILE;
        const __nv_bfloat16* s0 =
            g_wob + (size_t)(k0 + c0row) * V_ + v0 + c0col * 8;
        const __nv_bfloat16* s1 =
            g_wob + (size_t)(k0 + c1row) * V_ + v0 + c1col * 8;
        CP_ASYNC16(dbase + c0row * BS_LDB + c0col * 16, (const char*)s0);
        CP_ASYNC16(dbase + c1row * BS_LDB + c1col * 16, (const char*)s1);
    };

#pragma unroll
    for (int st = 0; st < 3; ++st) { issue_stage(st); CP_COMMIT(); }

    float rAcc[4][2];
#pragma unroll
    for (int mi = 0; mi < 4; ++mi) { rAcc[mi][0] = 0.f; rAcc[mi][1] = 0.f; }

    float acc[4][4][4];
#pragma unroll
    for (int mi = 0; mi < 4; ++mi)
#pragma unroll
        for (int ni = 0; ni < 4; ++ni)
#pragma unroll
            for (int j = 0; j < 4; ++j) acc[mi][ni][j] = 0.0f;

    for (int g = 0; g < NSTAGES; ++g) {
        CP_WAIT2();
        __syncthreads();
        if (g + 3 < NSTAGES) issue_stage(g + 3);
        CP_COMMIT();

        const uint32_t bufOff = (g & 3) * CLS_B_TILE;
        const uint32_t aOff = (g & 7) * 64;
#pragma unroll
        for (int s = 0; s < 2; ++s) {
            uint32_t a[4][4], bb[2][4];
#pragma unroll
            for (int mi = 0; mi < 4; ++mi)
                ldsm_x4(a[mi], aBase[mi] + aOff + s * 32);
#pragma unroll
            for (int ng = 0; ng < 2; ++ng)
                ldsm_x4_t(bb[ng], bBase[ng] + bufOff + s * 16 * BS_LDB);
#pragma unroll
            for (int mi = 0; mi < 4; ++mi)
#pragma unroll
                for (int ni = 0; ni < 4; ++ni)
                    mma_bf16(acc[mi][ni], a[mi],
                             bb[ni >> 1][(ni & 1) * 2],
                             bb[ni >> 1][(ni & 1) * 2 + 1]);
        }

        if ((g & 7) == 7) {
            const int v0 = v_base + (g >> 3) * CLS_BN;
            const float* bop = bo + v0 + wn * 32 + (lane & 3) * 2;
#pragma unroll
            for (int ni = 0; ni < 4; ++ni) {
                float2 bv = *(const float2*)(bop + ni * 8);
                float b0 = bv.x * LOG2E, b1 = bv.y * LOG2E;
#pragma unroll
                for (int mi = 0; mi < 4; ++mi) {
                    rAcc[mi][0] += ex2f(fmaf(acc[mi][ni][0], LOG2E, b0))
                                 + ex2f(fmaf(acc[mi][ni][1], LOG2E, b1));
                    rAcc[mi][1] += ex2f(fmaf(acc[mi][ni][2], LOG2E, b0))
                                 + ex2f(fmaf(acc[mi][ni][3], LOG2E, b1));
                    acc[mi][ni][0] = 0.f; acc[mi][ni][1] = 0.f;
                    acc[mi][ni][2] = 0.f; acc[mi][ni][3] = 0.f;
                }
            }
        }
    }
    CP_WAITALL();

#pragma unroll
    for (int mi = 0; mi < 4; ++mi)
#pragma unroll
        for (int hi = 0; hi < 2; ++hi) {
            float v = rAcc[mi][hi];
            v += __shfl_xor_sync(0xFFFFFFFFu, v, 1);
            v += __shfl_xor_sync(0xFFFFFFFFu, v, 2);
            if ((lane & 3) == 0)
                atomicAdd(&red[wm * 64 + mi * 16 + hi * 8 + (lane >> 2)], v);
        }
    __syncthreads();
    if (tid < 128)
        g_partial[(size_t)(l0 + tid) * NSPLIT + blockIdx.y] = red[tid];
}

// ---------------------------------------------------------------------------
// loss: per-row fp32 tag logit + log(sum partials) + global sum
// ---------------------------------------------------------------------------
__global__ void loss_kernel(const float* __restrict__ Wo,
                            const float* __restrict__ bo,
                            const int* __restrict__ tags,
                            float* __restrict__ out) {
    const int warp = (blockIdx.x * blockDim.x + threadIdx.x) >> 5;
    const int lane = threadIdx.x & 31;
    const int nwarps = (gridDim.x * blockDim.x) >> 5;
    float local = 0.0f;
    for (int l = warp; l < L_; l += nwarps) {
        int tag = tags[l];
        float dot = 0.0f;
#pragma unroll
        for (int j = 0; j < 8; ++j) {
            int k = lane + j * 32;
            dot += g_feat[(size_t)l * 256 + k] * Wo[(size_t)k * V_ + tag];
        }
        float ps = 0.0f;
        for (int sp = lane; sp < NSPLIT; sp += 32)
            ps += g_partial[(size_t)l * NSPLIT + sp];
#pragma unroll
        for (int off = 16; off > 0; off >>= 1) {
            dot += __shfl_down_sync(0xFFFFFFFFu, dot, off);
            ps  += __shfl_down_sync(0xFFFFFFFFu, ps, off);
        }
        if (lane == 0)
            local += logf(ps) - (dot + bo[tag]);
    }
    if (lane == 0)
        atomicAdd(out, local * (1.0f / (4096.0f + 1e-5f)));
}

// ---------------------------------------------------------------------------
// Launch. Inputs: hidden, begins, ends, bids, tags, W1, b1, W2, b2, Wo, bo
// ---------------------------------------------------------------------------
extern "C" void kernel_launch(void* const* d_in, const int* in_sizes, int n_in,
                              void* d_out, int out_size) {
    const float* hidden = (const float*)d_in[0];
    const int*   begins = (const int*)d_in[1];
    const int*   ends   = (const int*)d_in[2];
    const int*   bids   = (const int*)d_in[3];
    const int*   tags   = (const int*)d_in[4];
    const float* W1     = (const float*)d_in[5];
    const float* b1     = (const float*)d_in[6];
    const float* W2     = (const float*)d_in[7];
    const float* b2     = (const float*)d_in[8];
    const float* Wo     = (const float*)d_in[9];
    const float* bo     = (const float*)d_in[10];
    float* out = (float*)d_out;

    __nv_bfloat16 *spanb, *h1b, *featb, *w1b, *w2b, *wob;
    float* feat;
    cudaGetSymbolAddress((void**)&spanb, g_spanb);
    cudaGetSymbolAddress((void**)&h1b, g_h1b);
    cudaGetSymbolAddress((void**)&feat, g_feat);
    cudaGetSymbolAddress((void**)&featb, g_featb);
    cudaGetSymbolAddress((void**)&w1b, g_w1b);
    cudaGetSymbolAddress((void**)&w2b, g_w2b);
    cudaGetSymbolAddress((void**)&wob, g_wob);

    // opt-in dynamic smem limits (both wgemm instantiations + cls)
    cudaFuncSetAttribute(wgemm_kernel<3 * H_, 1>,
                         cudaFuncAttributeMaxDynamicSharedMemorySize,
                         WG_SMEM_BYTES);
    cudaFuncSetAttribute(wgemm_kernel<LAB_, 2>,
                         cudaFuncAttributeMaxDynamicSharedMemorySize,
                         WG_SMEM_BYTES);
    cudaFuncSetAttribute(cls_kernel,
                         cudaFuncAttributeMaxDynamicSharedMemorySize,
                         CLS_SMEM);

    // weight prep (bf16) + zero out
    prep_kernel<<<(N1_4 + N2_4 + 255) / 256, 256>>>(W1, W2, out);
    cvt_kernel<<<(LAB_ * V_ / 4 + 255) / 256, 256>>>(Wo, wob, LAB_ * V_ / 4);

    // 1) span embeddings (bf16)
    span_kernel<<<L_, 128>>>(hidden, begins, ends, bids);

    // 2) h1 = sigmoid(span @ W1 + b1) -> bf16
    {
        dim3 grid(L_ / 128, LAB_ / 64);
        wgemm_kernel<3 * H_, 1><<<grid, 256, WG_SMEM_BYTES>>>(
            spanb, w1b, b1, nullptr, h1b, LAB_);
    }
    // 3) feat = h1 @ W2 + b2 -> fp32 + bf16
    {
        dim3 grid(L_ / 128, LAB_ / 64);
        wgemm_kernel<LAB_, 2><<<grid, 256, WG_SMEM_BYTES>>>(
            h1b, w2b, b2, feat, featb, LAB_);
    }
    // 4) mma.sync classifier GEMM + fused exp-sum partials
    {
        dim3 grid(L_ / CLS_BM, NSPLIT);
        cls_kernel<<<grid, 256, CLS_SMEM>>>(bo);
    }
    // 5) final loss reduction
    loss_kernel<<<32, 256>>>(Wo, bo, tags, out);
}

// round 11
// speedup vs baseline: 1.3645x; 1.0873x over previous
#include <cuda_runtime.h>
#include <cuda_bf16.h>
#include <mma.h>
#include <math.h>
#include <stdint.h>

using namespace nvcuda;

// Problem constants
#define S_    2048
#define B_    16
#define H_    512
#define L_    4096
#define LAB_  256
#define V_    32000

// cls: persistent grid, rowblock-major work items
#define CLS_BM    128
#define CLS_BN    128
#define CLS_GRID  296                 // 2 CTAs x 148 SMs, one wave
#define N_RB      (L_ / CLS_BM)       // 32 rowblocks
#define N_VT      (V_ / CLS_BN)       // 250 v-tiles
#define N_ITEMS   (N_RB * N_VT)       // 8000

// cls smem (bytes)
#define AS_LDB   528                  // A row stride bytes (264 bf16)
#define BS_LDB   272                  // B row stride bytes (136 bf16)
#define CLS_A_OFF 0
#define CLS_A_BYTES (CLS_BM * AS_LDB)        // 67584
#define CLS_B_OFF  CLS_A_BYTES
#define CLS_B_TILE (32 * BS_LDB)             // 8704
#define CLS_B_BYTES (4 * CLS_B_TILE)         // 34816 (4-stage ring)
#define CLS_SMEM (CLS_B_OFF + CLS_B_BYTES)   // 102400 -> 2 CTAs/SM

// wgemm: BM=64, BN=64, 2-stage cp.async pipeline (fits 48KB default smem)
#define WCS_LD 36
#define WG_A_BUF (64 * 144)                  // 9216 per buf
#define WG_B_OFF (2 * WG_A_BUF)              // 18432
#define WG_SMEM_BYTES (WG_B_OFF + 2 * WG_A_BUF)  // 36864

// Scratch (static device globals)
__device__ __nv_bfloat16 g_spanb[(size_t)L_ * 3 * H_];
__device__ __nv_bfloat16 g_h1b[(size_t)L_ * LAB_];
__device__ float g_feat[(size_t)L_ * LAB_];
__device__ __nv_bfloat16 g_featb[(size_t)L_ * LAB_];
__device__ __nv_bfloat16 g_w1b[(size_t)3 * H_ * LAB_];
__device__ __nv_bfloat16 g_w2b[(size_t)LAB_ * LAB_];
__device__ __nv_bfloat16 g_wob[(size_t)LAB_ * V_];      // Wo bf16 [256][32000]
__device__ float g_rowsum[L_];                          // per-row exp sums

// ---------------------------------------------------------------------------
// PTX primitives (sm80-baseline)
// ---------------------------------------------------------------------------
__device__ __forceinline__ uint32_t smem_u32(const void* p) {
    uint32_t a;
    asm("{ .reg .u64 t; cvta.to.shared.u64 t, %1; cvt.u32.u64 %0, t; }"
        : "=r"(a) : "l"(p));
    return a;
}
__device__ __forceinline__ void ldsm_x4(uint32_t r[4], uint32_t addr) {
    asm volatile("ldmatrix.sync.aligned.m8n8.x4.shared.b16 {%0,%1,%2,%3}, [%4];"
        : "=r"(r[0]), "=r"(r[1]), "=r"(r[2]), "=r"(r[3]) : "r"(addr));
}
__device__ __forceinline__ void ldsm_x4_t(uint32_t r[4], uint32_t addr) {
    asm volatile("ldmatrix.sync.aligned.m8n8.x4.trans.shared.b16 {%0,%1,%2,%3}, [%4];"
        : "=r"(r[0]), "=r"(r[1]), "=r"(r[2]), "=r"(r[3]) : "r"(addr));
}
__device__ __forceinline__ void mma_bf16(float d[4], const uint32_t a[4],
                                         uint32_t b0, uint32_t b1) {
    asm volatile(
        "mma.sync.aligned.m16n8k16.row.col.f32.bf16.bf16.f32 "
        "{%0,%1,%2,%3}, {%4,%5,%6,%7}, {%8,%9}, {%0,%1,%2,%3};"
        : "+f"(d[0]), "+f"(d[1]), "+f"(d[2]), "+f"(d[3])
        : "r"(a[0]), "r"(a[1]), "r"(a[2]), "r"(a[3]), "r"(b0), "r"(b1));
}
#define CP_ASYNC16(dst, src) \
    asm volatile("cp.async.cg.shared.global [%0], [%1], 16;" \
        :: "r"(dst), "l"(src) : "memory")
#define CP_COMMIT() asm volatile("cp.async.commit_group;" ::: "memory")
#define CP_WAIT1()  asm volatile("cp.async.wait_group 1;" ::: "memory")
#define CP_WAIT2()  asm volatile("cp.async.wait_group 2;" ::: "memory")
#define CP_WAITALL() asm volatile("cp.async.wait_group 0;" ::: "memory")

__device__ __forceinline__ float ex2f(float x) {
    float r;
    asm("ex2.approx.f32 %0, %1;" : "=f"(r) : "f"(x));
    return r;
}

// ---------------------------------------------------------------------------
// fast exp poly (sigmoid epilogue in wgemm)
// ---------------------------------------------------------------------------
__device__ __forceinline__ float fast_exp(float x) {
    float z = x * 1.4426950408889634f;
    float r = rintf(z);
    float f = z - r;
    float p = 1.3333558146428443e-3f;
    p = fmaf(p, f, 9.6181291976036120e-3f);
    p = fmaf(p, f, 5.5504108664821580e-2f);
    p = fmaf(p, f, 2.4022650695910072e-1f);
    p = fmaf(p, f, 6.9314718055994531e-1f);
    p = fmaf(p, f, 1.0f);
    return __int_as_float(((int)r + 127) << 23) * p;
}

// ---------------------------------------------------------------------------
// span embeddings -> bf16 (float4, 2-way unrolled gather)
// ---------------------------------------------------------------------------
__global__ void span_kernel(const float* __restrict__ hidden,
                            const int* __restrict__ begins,
                            const int* __restrict__ ends,
                            const int* __restrict__ bids) {
    const int l = blockIdx.x;
    const int beg = begins[l];
    const int end = ends[l];
    const int b   = bids[l];
    const float inv_len = 1.0f / (float)(end - beg);
    const float4* hp = (const float4*)hidden;
    const int h4 = threadIdx.x;            // 0..127
    const int H4 = H_ / 4;

    float4 left  = hp[((size_t)(beg - 1) * B_ + b) * H4 + h4];
    float4 right = hp[((size_t)end * B_ + b) * H4 + h4];
    float4 s0 = make_float4(0.f, 0.f, 0.f, 0.f);
    float4 s1 = make_float4(0.f, 0.f, 0.f, 0.f);
    int t = beg;
    for (; t + 2 <= end; t += 2) {
        float4 v0 = hp[((size_t)t * B_ + b) * H4 + h4];
        float4 v1 = hp[((size_t)(t + 1) * B_ + b) * H4 + h4];
        s0.x += v0.x; s0.y += v0.y; s0.z += v0.z; s0.w += v0.w;
        s1.x += v1.x; s1.y += v1.y; s1.z += v1.z; s1.w += v1.w;
    }
    if (t < end) {
        float4 v0 = hp[((size_t)t * B_ + b) * H4 + h4];
        s0.x += v0.x; s0.y += v0.y; s0.z += v0.z; s0.w += v0.w;
    }
    s0.x += s1.x; s0.y += s1.y; s0.z += s1.z; s0.w += s1.w;

    __nv_bfloat16* out = g_spanb + (size_t)l * (3 * H_);
    uint2 pk;
    pk.x = __nv_bfloat162_raw(__floats2bfloat162_rn(left.x, left.y)).x;
    pk.y = __nv_bfloat162_raw(__floats2bfloat162_rn(left.z, left.w)).x;
    *(uint2*)&out[h4 * 4] = pk;
    pk.x = __nv_bfloat162_raw(__floats2bfloat162_rn(s0.x * inv_len, s0.y * inv_len)).x;
    pk.y = __nv_bfloat162_raw(__floats2bfloat162_rn(s0.z * inv_len, s0.w * inv_len)).x;
    *(uint2*)&out[H_ + h4 * 4] = pk;
    pk.x = __nv_bfloat162_raw(__floats2bfloat162_rn(right.x, right.y)).x;
    pk.y = __nv_bfloat162_raw(__floats2bfloat162_rn(right.z, right.w)).x;
    *(uint2*)&out[2 * H_ + h4 * 4] = pk;
}

// ---------------------------------------------------------------------------
// prep: W1+W2 -> bf16, zero out + g_rowsum (fused launches)
// ---------------------------------------------------------------------------
#define N1_4 (3 * H_ * LAB_ / 4)
#define N2_4 (LAB_ * LAB_ / 4)
__global__ void prep_kernel(const float* __restrict__ W1,
                            const float* __restrict__ W2,
                            float* __restrict__ out) {
    int i = blockIdx.x * blockDim.x + threadIdx.x;
    if (i == 0) out[0] = 0.0f;
    if (i < L_) g_rowsum[i] = 0.0f;
    if (i < N1_4) {
        float4 v = ((const float4*)W1)[i];
        ((__nv_bfloat162*)g_w1b)[2 * i]     = __floats2bfloat162_rn(v.x, v.y);
        ((__nv_bfloat162*)g_w1b)[2 * i + 1] = __floats2bfloat162_rn(v.z, v.w);
    } else if (i < N1_4 + N2_4) {
        int j = i - N1_4;
        float4 v = ((const float4*)W2)[j];
        ((__nv_bfloat162*)g_w2b)[2 * j]     = __floats2bfloat162_rn(v.x, v.y);
        ((__nv_bfloat162*)g_w2b)[2 * j + 1] = __floats2bfloat162_rn(v.z, v.w);
    }
}

// ---------------------------------------------------------------------------
// fp32 -> bf16 conversion (Wo)
// ---------------------------------------------------------------------------
__global__ void cvt_kernel(const float* __restrict__ src,
                           __nv_bfloat16* __restrict__ dst, int n4) {
    int i = blockIdx.x * blockDim.x + threadIdx.x;
    if (i < n4) {
        float4 v = ((const float4*)src)[i];
        ((__nv_bfloat162*)dst)[2 * i]     = __floats2bfloat162_rn(v.x, v.y);
        ((__nv_bfloat162*)dst)[2 * i + 1] = __floats2bfloat162_rn(v.z, v.w);
    }
}

// ---------------------------------------------------------------------------
// bf16 wmma GEMM for GEMM1/GEMM2. BM=64, BN=64, 2-stage cp.async pipeline.
// 8 warps = 4 row-groups x 2 col-groups (warp tile 16x32).
// grid (M/64, N/64) = (64, 4) = 256 CTAs.
// ---------------------------------------------------------------------------
template<int K, int EPI>
__global__ __launch_bounds__(256)
void wgemm_kernel(const __nv_bfloat16* __restrict__ A,
                  const __nv_bfloat16* __restrict__ B,
                  const float* __restrict__ bias,
                  float* __restrict__ C32,
                  __nv_bfloat16* __restrict__ Cb, int N) {
    extern __shared__ char smem[];
    const uint32_t sb = smem_u32(smem);
    float* Cs = (float*)smem;   // epilogue alias

    const int tid = threadIdx.x;
    const int wid = tid >> 5;
    const int lane = tid & 31;
    const int wm = wid >> 1;     // 0..3
    const int wn = wid & 1;      // 0..1
    const int m0 = blockIdx.x * 64;
    const int n0 = blockIdx.y * 64;
    constexpr int NIT = K / 64;

    auto issue = [&](int it) {
        const int k0 = it * 64;
        const int buf = it & 1;
        const uint32_t aDst = sb + buf * WG_A_BUF;
        const uint32_t bDst = sb + WG_B_OFF + buf * WG_A_BUF;
#pragma unroll
        for (int t = tid; t < 64 * 8; t += 256) {
            int m = t >> 3, k8 = t & 7;
            CP_ASYNC16(aDst + m * 144 + k8 * 16,
                       (const char*)&A[(size_t)(m0 + m) * K + k0 + k8 * 8]);
        }
#pragma unroll
        for (int t = tid; t < 64 * 8; t += 256) {
            int k = t >> 3, n8 = t & 7;
            CP_ASYNC16(bDst + k * 144 + n8 * 16,
                       (const char*)&B[(size_t)(k0 + k) * N + n0 + n8 * 8]);
        }
    };

    wmma::fragment<wmma::accumulator, 16, 16, 16, float> acc[2];
#pragma unroll
    for (int j = 0; j < 2; ++j) wmma::fill_fragment(acc[j], 0.0f);

    issue(0); CP_COMMIT();
    for (int it = 0; it < NIT; ++it) {
        if (it + 1 < NIT) { issue(it + 1); CP_COMMIT(); CP_WAIT1(); }
        else              { CP_WAITALL(); }
        __syncthreads();
        const int buf = it & 1;
        const __nv_bfloat16* As = (const __nv_bfloat16*)(smem + buf * WG_A_BUF);
        const __nv_bfloat16* Bs = (const __nv_bfloat16*)(smem + WG_B_OFF + buf * WG_A_BUF);
#pragma unroll
        for (int ks = 0; ks < 4; ++ks) {
            wmma::fragment<wmma::matrix_a, 16, 16, 16, __nv_bfloat16, wmma::row_major> af;
            wmma::load_matrix_sync(af, &As[(wm * 16) * 72 + ks * 16], 72);
#pragma unroll
            for (int nt = 0; nt < 2; ++nt) {
                wmma::fragment<wmma::matrix_b, 16, 16, 16, __nv_bfloat16, wmma::row_major> bf;
                wmma::load_matrix_sync(bf, &Bs[(ks * 16) * 72 + wn * 32 + nt * 16], 72);
                wmma::mma_sync(acc[nt], af, bf, acc[nt]);
            }
        }
        __syncthreads();
    }

    float* Cw = Cs + wid * 16 * WCS_LD;
#pragma unroll
    for (int nt = 0; nt < 2; ++nt)
        wmma::store_matrix_sync(&Cw[nt * 16], acc[nt], WCS_LD, wmma::mem_row_major);
    __syncwarp();

#pragma unroll
    for (int e = 0; e < 16; ++e) {
        int idx = lane + e * 32;
        int r = idx >> 5, c = idx & 31;
        int gr = m0 + wm * 16 + r;
        int gc = n0 + wn * 32 + c;
        float v = Cw[r * WCS_LD + c] + bias[gc];
        if (EPI == 1) {
            v = 1.0f / (1.0f + fast_exp(-v));
            Cb[(size_t)gr * N + gc] = __float2bfloat16(v);
        } else {
            C32[(size_t)gr * N + gc] = v;
            Cb[(size_t)gr * N + gc] = __float2bfloat16(v);
        }
    }
}

// ---------------------------------------------------------------------------
// cls: PERSISTENT mma.sync bf16 classifier GEMM + fused per-row exp-sums.
// grid = 296 (2 CTAs/SM, one wave). Work = 8000 items (rb, vtile),
// rowblock-major; CTA b owns items [b*8000/296, (b+1)*8000/296).
// A restaged only when rowblock changes (<=2 per CTA). Row exp-sums flushed
// by atomicAdd into g_rowsum.
// ---------------------------------------------------------------------------
__global__ __launch_bounds__(256, 2)
void cls_kernel(const float* __restrict__ bo) {
    extern __shared__ char smem[];
    const uint32_t sb = smem_u32(smem);

    const int tid = threadIdx.x;
    const int wid = tid >> 5;
    const int lane = tid & 31;
    const int wm = wid >> 2;          // 0..1 (row group of 64)
    const int wn = wid & 3;           // 0..3 (col group of 32)
    const float LOG2E = 1.4426950408889634f;

    const int start = (blockIdx.x * N_ITEMS) / CLS_GRID;
    const int end   = ((blockIdx.x + 1) * N_ITEMS) / CLS_GRID;
    const int NST   = (end - start) * 8;

    const int c0row = tid >> 4, c0col = tid & 15;
    const int c1row = (tid + 256) >> 4, c1col = (tid + 256) & 15;

    uint32_t aBase[4];
#pragma unroll
    for (int mi = 0; mi < 4; ++mi)
        aBase[mi] = sb + CLS_A_OFF
                  + (wm * 64 + mi * 16 + (lane & 15)) * AS_LDB
                  + (lane >> 4) * 16;
    uint32_t bBase[2];
#pragma unroll
    for (int ng = 0; ng < 2; ++ng)
        bBase[ng] = sb + CLS_B_OFF + (lane & 15) * BS_LDB
                  + (wn * 32 + ng * 16) * 2 + (lane >> 4) * 16;

    auto issue_stage = [&](int gs) {
        const int item = start + (gs >> 3);
        const int k0 = (gs & 7) * 32;
        const int v0 = (item % N_VT) * CLS_BN;
        const uint32_t dbase = sb + CLS_B_OFF + (gs & 3) * CLS_B_TILE;
        const __nv_bfloat16* s0 =
            g_wob + (size_t)(k0 + c0row) * V_ + v0 + c0col * 8;
        const __nv_bfloat16* s1 =
            g_wob + (size_t)(k0 + c1row) * V_ + v0 + c1col * 8;
        CP_ASYNC16(dbase + c0row * BS_LDB + c0col * 16, (const char*)s0);
        CP_ASYNC16(dbase + c1row * BS_LDB + c1col * 16, (const char*)s1);
    };

#pragma unroll
    for (int st = 0; st < 3; ++st) { issue_stage(st); CP_COMMIT(); }

    float rAcc[4][2];
#pragma unroll
    for (int mi = 0; mi < 4; ++mi) { rAcc[mi][0] = 0.f; rAcc[mi][1] = 0.f; }

    float acc[4][4][4];
#pragma unroll
    for (int mi = 0; mi < 4; ++mi)
#pragma unroll
        for (int ni = 0; ni < 4; ++ni)
#pragma unroll
            for (int j = 0; j < 4; ++j) acc[mi][ni][j] = 0.0f;

    int cur_rb = -1;

    auto flush = [&](int rb) {
#pragma unroll
        for (int mi = 0; mi < 4; ++mi)
#pragma unroll
            for (int hi = 0; hi < 2; ++hi) {
                float v = rAcc[mi][hi];
                v += __shfl_xor_sync(0xFFFFFFFFu, v, 1);
                v += __shfl_xor_sync(0xFFFFFFFFu, v, 2);
                if ((lane & 3) == 0)
                    atomicAdd(&g_rowsum[rb * CLS_BM + wm * 64 + mi * 16
                                        + hi * 8 + (lane >> 2)], v);
                rAcc[mi][hi] = 0.0f;
            }
    };

    for (int gs = 0; gs < NST; ++gs) {
        CP_WAIT2();
        __syncthreads();
        if (gs + 3 < NST) issue_stage(gs + 3);
        CP_COMMIT();

        const int item = start + (gs >> 3);
        if ((gs & 7) == 0) {
            const int rb = item / N_VT;
            if (rb != cur_rb) {
                if (cur_rb >= 0) flush(cur_rb);
                // stage A for this rowblock
                const __nv_bfloat16* src = g_featb + (size_t)rb * CLS_BM * LAB_;
#pragma unroll
                for (int t = tid; t < CLS_BM * 32; t += 256) {
                    int r = t >> 5, k8 = t & 31;
                    uint4 v = *(const uint4*)&src[(size_t)r * LAB_ + k8 * 8];
                    *(uint4*)(smem + CLS_A_OFF + r * AS_LDB + k8 * 16) = v;
                }
                __syncthreads();
                cur_rb = rb;
            }
        }

        const uint32_t bufOff = (gs & 3) * CLS_B_TILE;
        const uint32_t aOff = (gs & 7) * 64;
#pragma unroll
        for (int s = 0; s < 2; ++s) {
            uint32_t a[4][4], bb[2][4];
#pragma unroll
            for (int mi = 0; mi < 4; ++mi)
                ldsm_x4(a[mi], aBase[mi] + aOff + s * 32);
#pragma unroll
            for (int ng = 0; ng < 2; ++ng)
                ldsm_x4_t(bb[ng], bBase[ng] + bufOff + s * 16 * BS_LDB);
#pragma unroll
            for (int mi = 0; mi < 4; ++mi)
#pragma unroll
                for (int ni = 0; ni < 4; ++ni)
                    mma_bf16(acc[mi][ni], a[mi],
                             bb[ni >> 1][(ni & 1) * 2],
                             bb[ni >> 1][(ni & 1) * 2 + 1]);
        }

        if ((gs & 7) == 7) {
            const int v0 = (item % N_VT) * CLS_BN;
            const float* bop = bo + v0 + wn * 32 + (lane & 3) * 2;
#pragma unroll
            for (int ni = 0; ni < 4; ++ni) {
                float2 bv = *(const float2*)(bop + ni * 8);
                float b0 = bv.x * LOG2E, b1 = bv.y * LOG2E;
#pragma unroll
                for (int mi = 0; mi < 4; ++mi) {
                    rAcc[mi][0] += ex2f(fmaf(acc[mi][ni][0], LOG2E, b0))
                                 + ex2f(fmaf(acc[mi][ni][1], LOG2E, b1));
                    rAcc[mi][1] += ex2f(fmaf(acc[mi][ni][2], LOG2E, b0))
                                 + ex2f(fmaf(acc[mi][ni][3], LOG2E, b1));
                    acc[mi][ni][0] = 0.f; acc[mi][ni][1] = 0.f;
                    acc[mi][ni][2] = 0.f; acc[mi][ni][3] = 0.f;
                }
            }
        }
    }
    CP_WAITALL();
    if (cur_rb >= 0) flush(cur_rb);
}

// ---------------------------------------------------------------------------
// loss: per-row fp32 tag logit + log(rowsum) + global sum
// ---------------------------------------------------------------------------
__global__ void loss_kernel(const float* __restrict__ Wo,
                            const float* __restrict__ bo,
                            const int* __restrict__ tags,
                            float* __restrict__ out) {
    const int warp = (blockIdx.x * blockDim.x + threadIdx.x) >> 5;
    const int lane = threadIdx.x & 31;
    const int nwarps = (gridDim.x * blockDim.x) >> 5;
    float local = 0.0f;
    for (int l = warp; l < L_; l += nwarps) {
        int tag = tags[l];
        float dot = 0.0f;
#pragma unroll
        for (int j = 0; j < 8; ++j) {
            int k = lane + j * 32;
            dot += g_feat[(size_t)l * 256 + k] * Wo[(size_t)k * V_ + tag];
        }
#pragma unroll
        for (int off = 16; off > 0; off >>= 1)
            dot += __shfl_down_sync(0xFFFFFFFFu, dot, off);
        if (lane == 0)
            local += logf(g_rowsum[l]) - (dot + bo[tag]);
    }
    if (lane == 0)
        atomicAdd(out, local * (1.0f / (4096.0f + 1e-5f)));
}

// ---------------------------------------------------------------------------
// Launch. Inputs: hidden, begins, ends, bids, tags, W1, b1, W2, b2, Wo, bo
// ---------------------------------------------------------------------------
extern "C" void kernel_launch(void* const* d_in, const int* in_sizes, int n_in,
                              void* d_out, int out_size) {
    const float* hidden = (const float*)d_in[0];
    const int*   begins = (const int*)d_in[1];
    const int*   ends   = (const int*)d_in[2];
    const int*   bids   = (const int*)d_in[3];
    const int*   tags   = (const int*)d_in[4];
    const float* W1     = (const float*)d_in[5];
    const float* b1     = (const float*)d_in[6];
    const float* W2     = (const float*)d_in[7];
    const float* b2     = (const float*)d_in[8];
    const float* Wo     = (const float*)d_in[9];
    const float* bo     = (const float*)d_in[10];
    float* out = (float*)d_out;

    __nv_bfloat16 *spanb, *h1b, *featb, *w1b, *w2b, *wob;
    float* feat;
    cudaGetSymbolAddress((void**)&spanb, g_spanb);
    cudaGetSymbolAddress((void**)&h1b, g_h1b);
    cudaGetSymbolAddress((void**)&feat, g_feat);
    cudaGetSymbolAddress((void**)&featb, g_featb);
    cudaGetSymbolAddress((void**)&w1b, g_w1b);
    cudaGetSymbolAddress((void**)&w2b, g_w2b);
    cudaGetSymbolAddress((void**)&wob, g_wob);

    cudaFuncSetAttribute(cls_kernel,
                         cudaFuncAttributeMaxDynamicSharedMemorySize,
                         CLS_SMEM);

    // weight prep (bf16) + zero out + zero rowsums
    prep_kernel<<<(N1_4 + N2_4 + 255) / 256, 256>>>(W1, W2, out);
    cvt_kernel<<<(LAB_ * V_ / 4 + 255) / 256, 256>>>(Wo, wob, LAB_ * V_ / 4);

    // 1) span embeddings (bf16)
    span_kernel<<<L_, 128>>>(hidden, begins, ends, bids);

    // 2) h1 = sigmoid(span @ W1 + b1) -> bf16
    {
        dim3 grid(L_ / 64, LAB_ / 64);
        wgemm_kernel<3 * H_, 1><<<grid, 256, WG_SMEM_BYTES>>>(
            spanb, w1b, b1, nullptr, h1b, LAB_);
    }
    // 3) feat = h1 @ W2 + b2 -> fp32 + bf16
    {
        dim3 grid(L_ / 64, LAB_ / 64);
        wgemm_kernel<LAB_, 2><<<grid, 256, WG_SMEM_BYTES>>>(
            h1b, w2b, b2, feat, featb, LAB_);
    }
    // 4) persistent mma.sync classifier GEMM + fused exp-sum
    cls_kernel<<<CLS_GRID, 256, CLS_SMEM>>>(bo);

    // 5) final loss reduction
    loss_kernel<<<32, 256>>>(Wo, bo, tags, out);
}

// round 12
// speedup vs baseline: 1.4716x; 1.0785x over previous
#include <cuda_runtime.h>
#include <cuda_bf16.h>
#include <mma.h>
#include <math.h>
#include <stdint.h>

using namespace nvcuda;

// Problem constants
#define S_    2048
#define B_    16
#define H_    512
#define L_    4096
#define LAB_  256
#define V_    32000

// cls: persistent grid, rowblock-major work items, 128 threads (4 warps 2x2)
#define CLS_BM    128
#define CLS_BN    128
#define CLS_GRID  296                 // 2 CTAs x 148 SMs, one wave
#define N_RB      (L_ / CLS_BM)       // 32 rowblocks
#define N_VT      (V_ / CLS_BN)       // 250 v-tiles
#define N_ITEMS   (N_RB * N_VT)       // 8000

// cls smem (bytes)
#define AS_LDB   528                  // A row stride bytes (264 bf16)
#define BS_LDB   272                  // B row stride bytes (136 bf16)
#define CLS_A_OFF 0
#define CLS_A_BYTES (CLS_BM * AS_LDB)        // 67584
#define CLS_B_OFF  CLS_A_BYTES
#define CLS_B_TILE (32 * BS_LDB)             // 8704
#define CLS_B_BYTES (4 * CLS_B_TILE)         // 34816 (4-stage ring)
#define CLS_SMEM (CLS_B_OFF + CLS_B_BYTES)   // 102400 -> 2 CTAs/SM

// wgemm: BM=64, BN=64, 4-stage K=32 cp.async ring (fits 48KB default smem)
#define WCS_LD 36
#define WGA_LDB 80                    // A row stride bytes (32 bf16 + pad)
#define WGB_LDB 144                   // B row stride bytes (64 bf16 + pad)
#define WG_A_BYTES (64 * WGA_LDB)     // 5120
#define WG_STAGE (WG_A_BYTES + 32 * WGB_LDB)  // 9728
#define WG_SMEM_BYTES (4 * WG_STAGE)  // 38912

// Scratch (static device globals)
__device__ __nv_bfloat16 g_spanb[(size_t)L_ * 3 * H_];
__device__ __nv_bfloat16 g_h1b[(size_t)L_ * LAB_];
__device__ float g_feat[(size_t)L_ * LAB_];
__device__ __nv_bfloat16 g_featb[(size_t)L_ * LAB_];
__device__ __nv_bfloat16 g_w1b[(size_t)3 * H_ * LAB_];
__device__ __nv_bfloat16 g_w2b[(size_t)LAB_ * LAB_];
__device__ __nv_bfloat16 g_wob[(size_t)LAB_ * V_];      // Wo bf16 [256][32000]
__device__ float g_rowsum[L_];                          // per-row exp sums

// ---------------------------------------------------------------------------
// PTX primitives (sm80-baseline)
// ---------------------------------------------------------------------------
__device__ __forceinline__ uint32_t smem_u32(const void* p) {
    uint32_t a;
    asm("{ .reg .u64 t; cvta.to.shared.u64 t, %1; cvt.u32.u64 %0, t; }"
        : "=r"(a) : "l"(p));
    return a;
}
__device__ __forceinline__ void ldsm_x4(uint32_t r[4], uint32_t addr) {
    asm volatile("ldmatrix.sync.aligned.m8n8.x4.shared.b16 {%0,%1,%2,%3}, [%4];"
        : "=r"(r[0]), "=r"(r[1]), "=r"(r[2]), "=r"(r[3]) : "r"(addr));
}
__device__ __forceinline__ void ldsm_x4_t(uint32_t r[4], uint32_t addr) {
    asm volatile("ldmatrix.sync.aligned.m8n8.x4.trans.shared.b16 {%0,%1,%2,%3}, [%4];"
        : "=r"(r[0]), "=r"(r[1]), "=r"(r[2]), "=r"(r[3]) : "r"(addr));
}
__device__ __forceinline__ void mma_bf16(float d[4], const uint32_t a[4],
                                         uint32_t b0, uint32_t b1) {
    asm volatile(
        "mma.sync.aligned.m16n8k16.row.col.f32.bf16.bf16.f32 "
        "{%0,%1,%2,%3}, {%4,%5,%6,%7}, {%8,%9}, {%0,%1,%2,%3};"
        : "+f"(d[0]), "+f"(d[1]), "+f"(d[2]), "+f"(d[3])
        : "r"(a[0]), "r"(a[1]), "r"(a[2]), "r"(a[3]), "r"(b0), "r"(b1));
}
#define CP_ASYNC16(dst, src) \
    asm volatile("cp.async.cg.shared.global [%0], [%1], 16;" \
        :: "r"(dst), "l"(src) : "memory")
#define CP_COMMIT() asm volatile("cp.async.commit_group;" ::: "memory")
#define CP_WAIT2()  asm volatile("cp.async.wait_group 2;" ::: "memory")
#define CP_WAITALL() asm volatile("cp.async.wait_group 0;" ::: "memory")

__device__ __forceinline__ float ex2f(float x) {
    float r;
    asm("ex2.approx.f32 %0, %1;" : "=f"(r) : "f"(x));
    return r;
}

// ---------------------------------------------------------------------------
// fast exp poly (sigmoid epilogue in wgemm)
// ---------------------------------------------------------------------------
__device__ __forceinline__ float fast_exp(float x) {
    float z = x * 1.4426950408889634f;
    float r = rintf(z);
    float f = z - r;
    float p = 1.3333558146428443e-3f;
    p = fmaf(p, f, 9.6181291976036120e-3f);
    p = fmaf(p, f, 5.5504108664821580e-2f);
    p = fmaf(p, f, 2.4022650695910072e-1f);
    p = fmaf(p, f, 6.9314718055994531e-1f);
    p = fmaf(p, f, 1.0f);
    return __int_as_float(((int)r + 127) << 23) * p;
}

// ---------------------------------------------------------------------------
// span embeddings -> bf16 (float4, 2-way unrolled gather)
// ---------------------------------------------------------------------------
__global__ void span_kernel(const float* __restrict__ hidden,
                            const int* __restrict__ begins,
                            const int* __restrict__ ends,
                            const int* __restrict__ bids) {
    const int l = blockIdx.x;
    const int beg = begins[l];
    const int end = ends[l];
    const int b   = bids[l];
    const float inv_len = 1.0f / (float)(end - beg);
    const float4* hp = (const float4*)hidden;
    const int h4 = threadIdx.x;            // 0..127
    const int H4 = H_ / 4;

    float4 left  = hp[((size_t)(beg - 1) * B_ + b) * H4 + h4];
    float4 right = hp[((size_t)end * B_ + b) * H4 + h4];
    float4 s0 = make_float4(0.f, 0.f, 0.f, 0.f);
    float4 s1 = make_float4(0.f, 0.f, 0.f, 0.f);
    int t = beg;
    for (; t + 2 <= end; t += 2) {
        float4 v0 = hp[((size_t)t * B_ + b) * H4 + h4];
        float4 v1 = hp[((size_t)(t + 1) * B_ + b) * H4 + h4];
        s0.x += v0.x; s0.y += v0.y; s0.z += v0.z; s0.w += v0.w;
        s1.x += v1.x; s1.y += v1.y; s1.z += v1.z; s1.w += v1.w;
    }
    if (t < end) {
        float4 v0 = hp[((size_t)t * B_ + b) * H4 + h4];
        s0.x += v0.x; s0.y += v0.y; s0.z += v0.z; s0.w += v0.w;
    }
    s0.x += s1.x; s0.y += s1.y; s0.z += s1.z; s0.w += s1.w;

    __nv_bfloat16* out = g_spanb + (size_t)l * (3 * H_);
    uint2 pk;
    pk.x = __nv_bfloat162_raw(__floats2bfloat162_rn(left.x, left.y)).x;
    pk.y = __nv_bfloat162_raw(__floats2bfloat162_rn(left.z, left.w)).x;
    *(uint2*)&out[h4 * 4] = pk;
    pk.x = __nv_bfloat162_raw(__floats2bfloat162_rn(s0.x * inv_len, s0.y * inv_len)).x;
    pk.y = __nv_bfloat162_raw(__floats2bfloat162_rn(s0.z * inv_len, s0.w * inv_len)).x;
    *(uint2*)&out[H_ + h4 * 4] = pk;
    pk.x = __nv_bfloat162_raw(__floats2bfloat162_rn(right.x, right.y)).x;
    pk.y = __nv_bfloat162_raw(__floats2bfloat162_rn(right.z, right.w)).x;
    *(uint2*)&out[2 * H_ + h4 * 4] = pk;
}

// ---------------------------------------------------------------------------
// prep: W1+W2 -> bf16, zero out + g_rowsum (fused launches)
// ---------------------------------------------------------------------------
#define N1_4 (3 * H_ * LAB_ / 4)
#define N2_4 (LAB_ * LAB_ / 4)
__global__ void prep_kernel(const float* __restrict__ W1,
                            const float* __restrict__ W2,
                            float* __restrict__ out) {
    int i = blockIdx.x * blockDim.x + threadIdx.x;
    if (i == 0) out[0] = 0.0f;
    if (i < L_) g_rowsum[i] = 0.0f;
    if (i < N1_4) {
        float4 v = ((const float4*)W1)[i];
        ((__nv_bfloat162*)g_w1b)[2 * i]     = __floats2bfloat162_rn(v.x, v.y);
        ((__nv_bfloat162*)g_w1b)[2 * i + 1] = __floats2bfloat162_rn(v.z, v.w);
    } else if (i < N1_4 + N2_4) {
        int j = i - N1_4;
        float4 v = ((const float4*)W2)[j];
        ((__nv_bfloat162*)g_w2b)[2 * j]     = __floats2bfloat162_rn(v.x, v.y);
        ((__nv_bfloat162*)g_w2b)[2 * j + 1] = __floats2bfloat162_rn(v.z, v.w);
    }
}

// ---------------------------------------------------------------------------
// fp32 -> bf16 conversion (Wo)
// ---------------------------------------------------------------------------
__global__ void cvt_kernel(const float* __restrict__ src,
                           __nv_bfloat16* __restrict__ dst, int n4) {
    int i = blockIdx.x * blockDim.x + threadIdx.x;
    if (i < n4) {
        float4 v = ((const float4*)src)[i];
        ((__nv_bfloat162*)dst)[2 * i]     = __floats2bfloat162_rn(v.x, v.y);
        ((__nv_bfloat162*)dst)[2 * i + 1] = __floats2bfloat162_rn(v.z, v.w);
    }
}

// ---------------------------------------------------------------------------
// bf16 wmma GEMM for GEMM1/GEMM2. BM=64, BN=64, 4-stage K=32 cp.async ring.
// 8 warps = 4 row-groups x 2 col-groups (warp tile 16x32).
// grid (M/64, N/64) = (64, 4) = 256 CTAs.
// ---------------------------------------------------------------------------
template<int K, int EPI>
__global__ __launch_bounds__(256)
void wgemm_kernel(const __nv_bfloat16* __restrict__ A,
                  const __nv_bfloat16* __restrict__ B,
                  const float* __restrict__ bias,
                  float* __restrict__ C32,
                  __nv_bfloat16* __restrict__ Cb, int N) {
    extern __shared__ char smem[];
    const uint32_t sb = smem_u32(smem);
    float* Cs = (float*)smem;   // epilogue alias

    const int tid = threadIdx.x;
    const int wid = tid >> 5;
    const int lane = tid & 31;
    const int wm = wid >> 1;     // 0..3
    const int wn = wid & 1;      // 0..1
    const int m0 = blockIdx.x * 64;
    const int n0 = blockIdx.y * 64;
    constexpr int NIT = K / 32;

    // per-thread cp.async components (one A chunk + one B chunk per stage)
    const int ar = tid >> 2, akc = tid & 3;       // A: row 0..63, k-chunk 0..3
    const int brk = tid >> 3, bc = tid & 7;       // B: k-row 0..31, col-chunk 0..7

    auto issue = [&](int g) {
        const int k0 = g * 32;
        const uint32_t st = sb + (g & 3) * WG_STAGE;
        CP_ASYNC16(st + ar * WGA_LDB + akc * 16,
                   (const char*)&A[(size_t)(m0 + ar) * K + k0 + akc * 8]);
        CP_ASYNC16(st + WG_A_BYTES + brk * WGB_LDB + bc * 16,
                   (const char*)&B[(size_t)(k0 + brk) * N + n0 + bc * 8]);
    };

    wmma::fragment<wmma::accumulator, 16, 16, 16, float> acc[2];
#pragma unroll
    for (int j = 0; j < 2; ++j) wmma::fill_fragment(acc[j], 0.0f);

#pragma unroll
    for (int st = 0; st < 3; ++st) { issue(st); CP_COMMIT(); }

    for (int g = 0; g < NIT; ++g) {
        CP_WAIT2();
        __syncthreads();
        if (g + 3 < NIT) issue(g + 3);
        CP_COMMIT();
        const char* stage = smem + (g & 3) * WG_STAGE;
        const __nv_bfloat16* As = (const __nv_bfloat16*)stage;
        const __nv_bfloat16* Bs = (const __nv_bfloat16*)(stage + WG_A_BYTES);
#pragma unroll
        for (int ks = 0; ks < 2; ++ks) {
            wmma::fragment<wmma::matrix_a, 16, 16, 16, __nv_bfloat16, wmma::row_major> af;
            wmma::load_matrix_sync(af, &As[(wm * 16) * (WGA_LDB / 2) + ks * 16],
                                   WGA_LDB / 2);
#pragma unroll
            for (int nt = 0; nt < 2; ++nt) {
                wmma::fragment<wmma::matrix_b, 16, 16, 16, __nv_bfloat16, wmma::row_major> bf;
                wmma::load_matrix_sync(bf,
                    &Bs[(ks * 16) * (WGB_LDB / 2) + wn * 32 + nt * 16],
                    WGB_LDB / 2);
                wmma::mma_sync(acc[nt], af, bf, acc[nt]);
            }
        }
    }
    CP_WAITALL();
    __syncthreads();   // ring dead -> Cs alias safe

    float* Cw = Cs + wid * 16 * WCS_LD;
#pragma unroll
    for (int nt = 0; nt < 2; ++nt)
        wmma::store_matrix_sync(&Cw[nt * 16], acc[nt], WCS_LD, wmma::mem_row_major);
    __syncwarp();

#pragma unroll
    for (int e = 0; e < 16; ++e) {
        int idx = lane + e * 32;
        int r = idx >> 5, c = idx & 31;
        int gr = m0 + wm * 16 + r;
        int gc = n0 + wn * 32 + c;
        float v = Cw[r * WCS_LD + c] + bias[gc];
        if (EPI == 1) {
            v = 1.0f / (1.0f + fast_exp(-v));
            Cb[(size_t)gr * N + gc] = __float2bfloat16(v);
        } else {
            C32[(size_t)gr * N + gc] = v;
            Cb[(size_t)gr * N + gc] = __float2bfloat16(v);
        }
    }
}

// ---------------------------------------------------------------------------
// cls: PERSISTENT mma.sync bf16 classifier GEMM + fused per-row exp-sums.
// 128 threads = 4 warps, 2x2 grid of 64x64 warp tiles (A repl x2, B repl x2
// -> 32KB smem fragment traffic per K=32 stage vs 1024 tensor cycles).
// grid = 296 (2 CTAs/SM). Work = 8000 items (rb, vtile), rowblock-major.
// ---------------------------------------------------------------------------
__global__ __launch_bounds__(128, 2)
void cls_kernel(const float* __restrict__ bo) {
    extern __shared__ char smem[];
    const uint32_t sb = smem_u32(smem);

    const int tid = threadIdx.x;
    const int wid = tid >> 5;
    const int lane = tid & 31;
    const int wm = wid >> 1;          // 0..1 (row group of 64)
    const int wn = wid & 1;           // 0..1 (col group of 64)
    const float LOG2E = 1.4426950408889634f;

    const int start = (blockIdx.x * N_ITEMS) / CLS_GRID;
    const int end   = ((blockIdx.x + 1) * N_ITEMS) / CLS_GRID;
    const int NST   = (end - start) * 8;

    // B cp.async: 512 chunks of 16B per stage, 4 per thread
    // chunk c = tid + i*128: row = c>>4 (k 0..31), col16 = c&15
    uint32_t aBase[4];
#pragma unroll
    for (int mi = 0; mi < 4; ++mi)
        aBase[mi] = sb + CLS_A_OFF
                  + (wm * 64 + mi * 16 + (lane & 15)) * AS_LDB
                  + (lane >> 4) * 16;
    uint32_t bBase[4];
#pragma unroll
    for (int ng = 0; ng < 4; ++ng)
        bBase[ng] = sb + CLS_B_OFF + (lane & 15) * BS_LDB
                  + (wn * 64 + ng * 16) * 2 + (lane >> 4) * 16;

    auto issue_stage = [&](int gs) {
        const int item = start + (gs >> 3);
        const int k0 = (gs & 7) * 32;
        const int v0 = (item % N_VT) * CLS_BN;
        const uint32_t dbase = sb + CLS_B_OFF + (gs & 3) * CLS_B_TILE;
#pragma unroll
        for (int i = 0; i < 4; ++i) {
            int c = tid + i * 128;
            int row = c >> 4, col = c & 15;
            CP_ASYNC16(dbase + row * BS_LDB + col * 16,
                       (const char*)(g_wob + (size_t)(k0 + row) * V_
                                     + v0 + col * 8));
        }
    };

#pragma unroll
    for (int st = 0; st < 3; ++st) { issue_stage(st); CP_COMMIT(); }

    float rAcc[4][2];
#pragma unroll
    for (int mi = 0; mi < 4; ++mi) { rAcc[mi][0] = 0.f; rAcc[mi][1] = 0.f; }

    float acc[4][8][4];
#pragma unroll
    for (int mi = 0; mi < 4; ++mi)
#pragma unroll
        for (int ni = 0; ni < 8; ++ni)
#pragma unroll
            for (int j = 0; j < 4; ++j) acc[mi][ni][j] = 0.0f;

    int cur_rb = -1;

    auto flush = [&](int rb) {
#pragma unroll
        for (int mi = 0; mi < 4; ++mi)
#pragma unroll
            for (int hi = 0; hi < 2; ++hi) {
                float v = rAcc[mi][hi];
                v += __shfl_xor_sync(0xFFFFFFFFu, v, 1);
                v += __shfl_xor_sync(0xFFFFFFFFu, v, 2);
                if ((lane & 3) == 0 && wn == 0)
                    ;   // placeholder (both wn halves must add; see below)
                if ((lane & 3) == 0)
                    atomicAdd(&g_rowsum[rb * CLS_BM + wm * 64 + mi * 16
                                        + hi * 8 + (lane >> 2)], v);
                rAcc[mi][hi] = 0.0f;
            }
    };

    for (int gs = 0; gs < NST; ++gs) {
        CP_WAIT2();
        __syncthreads();
        if (gs + 3 < NST) issue_stage(gs + 3);
        CP_COMMIT();

        const int item = start + (gs >> 3);
        if ((gs & 7) == 0) {
            const int rb = item / N_VT;
            if (rb != cur_rb) {
                if (cur_rb >= 0) flush(cur_rb);
                // stage A for this rowblock: 128 rows x 32 uint4 chunks
                const __nv_bfloat16* src = g_featb + (size_t)rb * CLS_BM * LAB_;
#pragma unroll
                for (int t = tid; t < CLS_BM * 32; t += 128) {
                    int r = t >> 5, k8 = t & 31;
                    uint4 v = *(const uint4*)&src[(size_t)r * LAB_ + k8 * 8];
                    *(uint4*)(smem + CLS_A_OFF + r * AS_LDB + k8 * 16) = v;
                }
                __syncthreads();
                cur_rb = rb;
            }
        }

        const uint32_t bufOff = (gs & 3) * CLS_B_TILE;
        const uint32_t aOff = (gs & 7) * 64;
#pragma unroll
        for (int s = 0; s < 2; ++s) {
            uint32_t a[4][4], bb[4][4];
#pragma unroll
            for (int mi = 0; mi < 4; ++mi)
                ldsm_x4(a[mi], aBase[mi] + aOff + s * 32);
#pragma unroll
            for (int ng = 0; ng < 4; ++ng)
                ldsm_x4_t(bb[ng], bBase[ng] + bufOff + s * 16 * BS_LDB);
#pragma unroll
            for (int mi = 0; mi < 4; ++mi)
#pragma unroll
                for (int ni = 0; ni < 8; ++ni)
                    mma_bf16(acc[mi][ni], a[mi],
                             bb[ni >> 1][(ni & 1) * 2],
                             bb[ni >> 1][(ni & 1) * 2 + 1]);
        }

        if ((gs & 7) == 7) {
            const int v0 = (item % N_VT) * CLS_BN;
            const float* bop = bo + v0 + wn * 64 + (lane & 3) * 2;
#pragma unroll
            for (int ni = 0; ni < 8; ++ni) {
                float2 bv = *(const float2*)(bop + ni * 8);
                float b0 = bv.x * LOG2E, b1 = bv.y * LOG2E;
#pragma unroll
                for (int mi = 0; mi < 4; ++mi) {
                    rAcc[mi][0] += ex2f(fmaf(acc[mi][ni][0], LOG2E, b0))
                                 + ex2f(fmaf(acc[mi][ni][1], LOG2E, b1));
                    rAcc[mi][1] += ex2f(fmaf(acc[mi][ni][2], LOG2E, b0))
                                 + ex2f(fmaf(acc[mi][ni][3], LOG2E, b1));
                    acc[mi][ni][0] = 0.f; acc[mi][ni][1] = 0.f;
                    acc[mi][ni][2] = 0.f; acc[mi][ni][3] = 0.f;
                }
            }
        }
    }
    CP_WAITALL();
    if (cur_rb >= 0) flush(cur_rb);
}

// ---------------------------------------------------------------------------
// loss: per-row fp32 tag logit + log(rowsum) + global sum
// ---------------------------------------------------------------------------
__global__ void loss_kernel(const float* __restrict__ Wo,
                            const float* __restrict__ bo,
                            const int* __restrict__ tags,
                            float* __restrict__ out) {
    const int warp = (blockIdx.x * blockDim.x + threadIdx.x) >> 5;
    const int lane = threadIdx.x & 31;
    const int nwarps = (gridDim.x * blockDim.x) >> 5;
    float local = 0.0f;
    for (int l = warp; l < L_; l += nwarps) {
        int tag = tags[l];
        float dot = 0.0f;
#pragma unroll
        for (int j = 0; j < 8; ++j) {
            int k = lane + j * 32;
            dot += g_feat[(size_t)l * 256 + k] * Wo[(size_t)k * V_ + tag];
        }
#pragma unroll
        for (int off = 16; off > 0; off >>= 1)
            dot += __shfl_down_sync(0xFFFFFFFFu, dot, off);
        if (lane == 0)
            local += logf(g_rowsum[l]) - (dot + bo[tag]);
    }
    if (lane == 0)
        atomicAdd(out, local * (1.0f / (4096.0f + 1e-5f)));
}

// ---------------------------------------------------------------------------
// Launch. Inputs: hidden, begins, ends, bids, tags, W1, b1, W2, b2, Wo, bo
// ---------------------------------------------------------------------------
extern "C" void kernel_launch(void* const* d_in, const int* in_sizes, int n_in,
                              void* d_out, int out_size) {
    const float* hidden = (const float*)d_in[0];
    const int*   begins = (const int*)d_in[1];
    const int*   ends   = (const int*)d_in[2];
    const int*   bids   = (const int*)d_in[3];
    const int*   tags   = (const int*)d_in[4];
    const float* W1     = (const float*)d_in[5];
    const float* b1     = (const float*)d_in[6];
    const float* W2     = (const float*)d_in[7];
    const float* b2     = (const float*)d_in[8];
    const float* Wo     = (const float*)d_in[9];
    const float* bo     = (const float*)d_in[10];
    float* out = (float*)d_out;

    __nv_bfloat16 *spanb, *h1b, *featb, *w1b, *w2b, *wob;
    float* feat;
    cudaGetSymbolAddress((void**)&spanb, g_spanb);
    cudaGetSymbolAddress((void**)&h1b, g_h1b);
    cudaGetSymbolAddress((void**)&feat, g_feat);
    cudaGetSymbolAddress((void**)&featb, g_featb);
    cudaGetSymbolAddress((void**)&w1b, g_w1b);
    cudaGetSymbolAddress((void**)&w2b, g_w2b);
    cudaGetSymbolAddress((void**)&wob, g_wob);

    cudaFuncSetAttribute(cls_kernel,
                         cudaFuncAttributeMaxDynamicSharedMemorySize,
                         CLS_SMEM);

    // weight prep (bf16) + zero out + zero rowsums
    prep_kernel<<<(N1_4 + N2_4 + 255) / 256, 256>>>(W1, W2, out);
    cvt_kernel<<<(LAB_ * V_ / 4 + 255) / 256, 256>>>(Wo, wob, LAB_ * V_ / 4);

    // 1) span embeddings (bf16)
    span_kernel<<<L_, 128>>>(hidden, begins, ends, bids);

    // 2) h1 = sigmoid(span @ W1 + b1) -> bf16
    {
        dim3 grid(L_ / 64, LAB_ / 64);
        wgemm_kernel<3 * H_, 1><<<grid, 256, WG_SMEM_BYTES>>>(
            spanb, w1b, b1, nullptr, h1b, LAB_);
    }
    // 3) feat = h1 @ W2 + b2 -> fp32 + bf16
    {
        dim3 grid(L_ / 64, LAB_ / 64);
        wgemm_kernel<LAB_, 2><<<grid, 256, WG_SMEM_BYTES>>>(
            h1b, w2b, b2, feat, featb, LAB_);
    }
    // 4) persistent mma.sync classifier GEMM + fused exp-sum
    cls_kernel<<<CLS_GRID, 128, CLS_SMEM>>>(bo);

    // 5) final loss reduction
    loss_kernel<<<32, 256>>>(Wo, bo, tags, out);
}

// round 13
// speedup vs baseline: 1.5025x; 1.0210x over previous
#include <cuda_runtime.h>
#include <cuda_bf16.h>
#include <math.h>
#include <stdint.h>

// Problem constants
#define S_    2048
#define B_    16
#define H_    512
#define L_    4096
#define LAB_  256
#define V_    32000

// cls: persistent grid, rowblock-major work items, 128 threads (4 warps 2x2)
#define CLS_BM    128
#define CLS_BN    128
#define CLS_GRID  296                 // 2 CTAs x 148 SMs, one wave
#define N_RB      (L_ / CLS_BM)       // 32 rowblocks
#define N_VT      (V_ / CLS_BN)       // 250 v-tiles
#define N_ITEMS   (N_RB * N_VT)       // 8000

// cls smem (bytes)
#define AS_LDB   528                  // A row stride bytes (264 bf16)
#define BS_LDB   272                  // B row stride bytes (136 bf16)
#define CLS_A_OFF 0
#define CLS_A_BYTES (CLS_BM * AS_LDB)        // 67584
#define CLS_B_OFF  CLS_A_BYTES
#define CLS_B_TILE (32 * BS_LDB)             // 8704
#define CLS_B_BYTES (4 * CLS_B_TILE)         // 34816 (4-stage ring)
#define CLS_SMEM (CLS_B_OFF + CLS_B_BYTES)   // 102400 -> 2 CTAs/SM

// wgemm (raw mma): BM=128, BN=64, 128 threads, 4-stage K=32 ring
#define WGA_LDB 80                    // A row stride bytes (32 bf16 + 16B pad)
#define WGB_LDB 272                   // B row stride bytes (64 bf16 + pad)
#define WG_A_BYTES (128 * WGA_LDB)    // 10240
#define WG_STAGE (WG_A_BYTES + 32 * WGB_LDB) // 18944
#define WG_SMEM_BYTES (4 * WG_STAGE)  // 75776

// Scratch (static device globals)
__device__ __nv_bfloat16 g_spanb[(size_t)L_ * 3 * H_];
__device__ __nv_bfloat16 g_h1b[(size_t)L_ * LAB_];
__device__ float g_feat[(size_t)L_ * LAB_];
__device__ __nv_bfloat16 g_featb[(size_t)L_ * LAB_];
__device__ __nv_bfloat16 g_w1b[(size_t)3 * H_ * LAB_];
__device__ __nv_bfloat16 g_w2b[(size_t)LAB_ * LAB_];
__device__ __nv_bfloat16 g_wob[(size_t)LAB_ * V_];      // Wo bf16 [256][32000]
__device__ float g_rowsum[L_];                          // per-row exp sums

// ---------------------------------------------------------------------------
// PTX primitives (sm80-baseline)
// ---------------------------------------------------------------------------
__device__ __forceinline__ uint32_t smem_u32(const void* p) {
    uint32_t a;
    asm("{ .reg .u64 t; cvta.to.shared.u64 t, %1; cvt.u32.u64 %0, t; }"
        : "=r"(a) : "l"(p));
    return a;
}
__device__ __forceinline__ void ldsm_x4(uint32_t r[4], uint32_t addr) {
    asm volatile("ldmatrix.sync.aligned.m8n8.x4.shared.b16 {%0,%1,%2,%3}, [%4];"
        : "=r"(r[0]), "=r"(r[1]), "=r"(r[2]), "=r"(r[3]) : "r"(addr));
}
__device__ __forceinline__ void ldsm_x4_t(uint32_t r[4], uint32_t addr) {
    asm volatile("ldmatrix.sync.aligned.m8n8.x4.trans.shared.b16 {%0,%1,%2,%3}, [%4];"
        : "=r"(r[0]), "=r"(r[1]), "=r"(r[2]), "=r"(r[3]) : "r"(addr));
}
__device__ __forceinline__ void mma_bf16(float d[4], const uint32_t a[4],
                                         uint32_t b0, uint32_t b1) {
    asm volatile(
        "mma.sync.aligned.m16n8k16.row.col.f32.bf16.bf16.f32 "
        "{%0,%1,%2,%3}, {%4,%5,%6,%7}, {%8,%9}, {%0,%1,%2,%3};"
        : "+f"(d[0]), "+f"(d[1]), "+f"(d[2]), "+f"(d[3])
        : "r"(a[0]), "r"(a[1]), "r"(a[2]), "r"(a[3]), "r"(b0), "r"(b1));
}
#define CP_ASYNC16(dst, src) \
    asm volatile("cp.async.cg.shared.global [%0], [%1], 16;" \
        :: "r"(dst), "l"(src) : "memory")
#define CP_COMMIT() asm volatile("cp.async.commit_group;" ::: "memory")
#define CP_WAIT2()  asm volatile("cp.async.wait_group 2;" ::: "memory")
#define CP_WAITALL() asm volatile("cp.async.wait_group 0;" ::: "memory")

__device__ __forceinline__ float ex2f(float x) {
    float r;
    asm("ex2.approx.f32 %0, %1;" : "=f"(r) : "f"(x));
    return r;
}

// ---------------------------------------------------------------------------
// fast exp poly (sigmoid epilogue in wgemm)
// ---------------------------------------------------------------------------
__device__ __forceinline__ float fast_exp(float x) {
    float z = x * 1.4426950408889634f;
    float r = rintf(z);
    float f = z - r;
    float p = 1.3333558146428443e-3f;
    p = fmaf(p, f, 9.6181291976036120e-3f);
    p = fmaf(p, f, 5.5504108664821580e-2f);
    p = fmaf(p, f, 2.4022650695910072e-1f);
    p = fmaf(p, f, 6.9314718055994531e-1f);
    p = fmaf(p, f, 1.0f);
    return __int_as_float(((int)r + 127) << 23) * p;
}

// ---------------------------------------------------------------------------
// span embeddings -> bf16 (float4, 2-way unrolled gather)
// ---------------------------------------------------------------------------
__global__ void span_kernel(const float* __restrict__ hidden,
                            const int* __restrict__ begins,
                            const int* __restrict__ ends,
                            const int* __restrict__ bids) {
    const int l = blockIdx.x;
    const int beg = begins[l];
    const int end = ends[l];
    const int b   = bids[l];
    const float inv_len = 1.0f / (float)(end - beg);
    const float4* hp = (const float4*)hidden;
    const int h4 = threadIdx.x;            // 0..127
    const int H4 = H_ / 4;

    float4 left  = hp[((size_t)(beg - 1) * B_ + b) * H4 + h4];
    float4 right = hp[((size_t)end * B_ + b) * H4 + h4];
    float4 s0 = make_float4(0.f, 0.f, 0.f, 0.f);
    float4 s1 = make_float4(0.f, 0.f, 0.f, 0.f);
    int t = beg;
    for (; t + 2 <= end; t += 2) {
        float4 v0 = hp[((size_t)t * B_ + b) * H4 + h4];
        float4 v1 = hp[((size_t)(t + 1) * B_ + b) * H4 + h4];
        s0.x += v0.x; s0.y += v0.y; s0.z += v0.z; s0.w += v0.w;
        s1.x += v1.x; s1.y += v1.y; s1.z += v1.z; s1.w += v1.w;
    }
    if (t < end) {
        float4 v0 = hp[((size_t)t * B_ + b) * H4 + h4];
        s0.x += v0.x; s0.y += v0.y; s0.z += v0.z; s0.w += v0.w;
    }
    s0.x += s1.x; s0.y += s1.y; s0.z += s1.z; s0.w += s1.w;

    __nv_bfloat16* out = g_spanb + (size_t)l * (3 * H_);
    uint2 pk;
    pk.x = __nv_bfloat162_raw(__floats2bfloat162_rn(left.x, left.y)).x;
    pk.y = __nv_bfloat162_raw(__floats2bfloat162_rn(left.z, left.w)).x;
    *(uint2*)&out[h4 * 4] = pk;
    pk.x = __nv_bfloat162_raw(__floats2bfloat162_rn(s0.x * inv_len, s0.y * inv_len)).x;
    pk.y = __nv_bfloat162_raw(__floats2bfloat162_rn(s0.z * inv_len, s0.w * inv_len)).x;
    *(uint2*)&out[H_ + h4 * 4] = pk;
    pk.x = __nv_bfloat162_raw(__floats2bfloat162_rn(right.x, right.y)).x;
    pk.y = __nv_bfloat162_raw(__floats2bfloat162_rn(right.z, right.w)).x;
    *(uint2*)&out[2 * H_ + h4 * 4] = pk;
}

// ---------------------------------------------------------------------------
// prep: W1+W2 -> bf16, zero out + g_rowsum (fused launches)
// ---------------------------------------------------------------------------
#define N1_4 (3 * H_ * LAB_ / 4)
#define N2_4 (LAB_ * LAB_ / 4)
__global__ void prep_kernel(const float* __restrict__ W1,
                            const float* __restrict__ W2,
                            float* __restrict__ out) {
    int i = blockIdx.x * blockDim.x + threadIdx.x;
    if (i == 0) out[0] = 0.0f;
    if (i < L_) g_rowsum[i] = 0.0f;
    if (i < N1_4) {
        float4 v = ((const float4*)W1)[i];
        ((__nv_bfloat162*)g_w1b)[2 * i]     = __floats2bfloat162_rn(v.x, v.y);
        ((__nv_bfloat162*)g_w1b)[2 * i + 1] = __floats2bfloat162_rn(v.z, v.w);
    } else if (i < N1_4 + N2_4) {
        int j = i - N1_4;
        float4 v = ((const float4*)W2)[j];
        ((__nv_bfloat162*)g_w2b)[2 * j]     = __floats2bfloat162_rn(v.x, v.y);
        ((__nv_bfloat162*)g_w2b)[2 * j + 1] = __floats2bfloat162_rn(v.z, v.w);
    }
}

// ---------------------------------------------------------------------------
// fp32 -> bf16 conversion (Wo)
// ---------------------------------------------------------------------------
__global__ void cvt_kernel(const float* __restrict__ src,
                           __nv_bfloat16* __restrict__ dst, int n4) {
    int i = blockIdx.x * blockDim.x + threadIdx.x;
    if (i < n4) {
        float4 v = ((const float4*)src)[i];
        ((__nv_bfloat162*)dst)[2 * i]     = __floats2bfloat162_rn(v.x, v.y);
        ((__nv_bfloat162*)dst)[2 * i + 1] = __floats2bfloat162_rn(v.z, v.w);
    }
}

// ---------------------------------------------------------------------------
// wgemm (raw mma.sync): C[M,N] = epi(A[M,K] @ B[K,N] + bias)
// BM=128, BN=64, 128 threads = 4 warps (2x2), warp tile 64x32.
// 4-stage K=32 cp.async ring; direct register epilogue.
// EPI 1: sigmoid -> bf16 Cb. EPI 2: bias -> fp32 C32 AND bf16 Cb.
// grid (M/128, N/64)
// ---------------------------------------------------------------------------
template<int K, int EPI>
__global__ __launch_bounds__(128)
void wgemm_kernel(const __nv_bfloat16* __restrict__ A,
                  const __nv_bfloat16* __restrict__ B,
                  const float* __restrict__ bias,
                  float* __restrict__ C32,
                  __nv_bfloat16* __restrict__ Cb, int N) {
    extern __shared__ char smem[];
    const uint32_t sb = smem_u32(smem);

    const int tid = threadIdx.x;
    const int wid = tid >> 5;
    const int lane = tid & 31;
    const int wm = wid >> 1;     // 0..1 (row group of 64)
    const int wn = wid & 1;      // 0..1 (col group of 32)
    const int m0 = blockIdx.x * 128;
    const int n0 = blockIdx.y * 64;
    constexpr int NIT = K / 32;

    auto issue = [&](int g) {
        const int k0 = g * 32;
        const uint32_t st = sb + (g & 3) * WG_STAGE;
        // A: 128 rows x 32 bf16 = 512 x 16B chunks, 4 per thread
#pragma unroll
        for (int i = 0; i < 4; ++i) {
            int c = tid + i * 128;
            int r = c >> 2, kc = c & 3;
            CP_ASYNC16(st + r * WGA_LDB + kc * 16,
                       (const char*)&A[(size_t)(m0 + r) * K + k0 + kc * 8]);
        }
        // B: 32 k-rows x 64 cols = 256 x 16B chunks, 2 per thread
#pragma unroll
        for (int i = 0; i < 2; ++i) {
            int c = tid + i * 128;
            int rk = c >> 3, cc = c & 7;
            CP_ASYNC16(st + WG_A_BYTES + rk * WGB_LDB + cc * 16,
                       (const char*)&B[(size_t)(k0 + rk) * N + n0 + cc * 8]);
        }
    };

    uint32_t aBase[4];
#pragma unroll
    for (int mi = 0; mi < 4; ++mi)
        aBase[mi] = sb + (wm * 64 + mi * 16 + (lane & 15)) * WGA_LDB
                  + (lane >> 4) * 16;
    uint32_t bBase[2];
#pragma unroll
    for (int ng = 0; ng < 2; ++ng)
        bBase[ng] = sb + WG_A_BYTES + (lane & 15) * WGB_LDB
                  + (wn * 32 + ng * 16) * 2 + (lane >> 4) * 16;

    float acc[4][4][4];
#pragma unroll
    for (int mi = 0; mi < 4; ++mi)
#pragma unroll
        for (int ni = 0; ni < 4; ++ni)
#pragma unroll
            for (int j = 0; j < 4; ++j) acc[mi][ni][j] = 0.0f;

#pragma unroll
    for (int st = 0; st < 3; ++st) { issue(st); CP_COMMIT(); }

    for (int g = 0; g < NIT; ++g) {
        CP_WAIT2();
        __syncthreads();
        if (g + 3 < NIT) issue(g + 3);
        CP_COMMIT();
        const uint32_t stOff = (g & 3) * WG_STAGE;
#pragma unroll
        for (int s = 0; s < 2; ++s) {
            uint32_t a[4][4], bb[2][4];
#pragma unroll
            for (int mi = 0; mi < 4; ++mi)
                ldsm_x4(a[mi], aBase[mi] + stOff + s * 32);
#pragma unroll
            for (int ng = 0; ng < 2; ++ng)
                ldsm_x4_t(bb[ng], bBase[ng] + stOff + s * 16 * WGB_LDB);
#pragma unroll
            for (int mi = 0; mi < 4; ++mi)
#pragma unroll
                for (int ni = 0; ni < 4; ++ni)
                    mma_bf16(acc[mi][ni], a[mi],
                             bb[ni >> 1][(ni & 1) * 2],
                             bb[ni >> 1][(ni & 1) * 2 + 1]);
        }
        __syncthreads();
    }
    CP_WAITALL();

    // direct register epilogue (m16n8k16 acc lane mapping)
#pragma unroll
    for (int mi = 0; mi < 4; ++mi) {
        const int r0 = m0 + wm * 64 + mi * 16 + (lane >> 2);
#pragma unroll
        for (int ni = 0; ni < 4; ++ni) {
            const int gc = n0 + wn * 32 + ni * 8 + (lane & 3) * 2;
            float2 bv = *(const float2*)&bias[gc];
            float v00 = acc[mi][ni][0] + bv.x;
            float v01 = acc[mi][ni][1] + bv.y;
            float v10 = acc[mi][ni][2] + bv.x;
            float v11 = acc[mi][ni][3] + bv.y;
            if (EPI == 1) {
                v00 = 1.0f / (1.0f + fast_exp(-v00));
                v01 = 1.0f / (1.0f + fast_exp(-v01));
                v10 = 1.0f / (1.0f + fast_exp(-v10));
                v11 = 1.0f / (1.0f + fast_exp(-v11));
                *(__nv_bfloat162*)&Cb[(size_t)r0 * N + gc] =
                    __floats2bfloat162_rn(v00, v01);
                *(__nv_bfloat162*)&Cb[(size_t)(r0 + 8) * N + gc] =
                    __floats2bfloat162_rn(v10, v11);
            } else {
                *(float2*)&C32[(size_t)r0 * N + gc] = make_float2(v00, v01);
                *(float2*)&C32[(size_t)(r0 + 8) * N + gc] = make_float2(v10, v11);
                *(__nv_bfloat162*)&Cb[(size_t)r0 * N + gc] =
                    __floats2bfloat162_rn(v00, v01);
                *(__nv_bfloat162*)&Cb[(size_t)(r0 + 8) * N + gc] =
                    __floats2bfloat162_rn(v10, v11);
            }
        }
    }
}

// ---------------------------------------------------------------------------
// cls: PERSISTENT mma.sync bf16 classifier GEMM + fused per-row exp-sums.
// 128 threads = 4 warps, 2x2 grid of 64x64 warp tiles.
// grid = 296 (2 CTAs/SM). Work = 8000 items (rb, vtile), rowblock-major.
// ---------------------------------------------------------------------------
__global__ __launch_bounds__(128, 2)
void cls_kernel(const float* __restrict__ bo) {
    extern __shared__ char smem[];
    const uint32_t sb = smem_u32(smem);

    const int tid = threadIdx.x;
    const int wid = tid >> 5;
    const int lane = tid & 31;
    const int wm = wid >> 1;          // 0..1 (row group of 64)
    const int wn = wid & 1;           // 0..1 (col group of 64)
    const float LOG2E = 1.4426950408889634f;

    const int start = (blockIdx.x * N_ITEMS) / CLS_GRID;
    const int end   = ((blockIdx.x + 1) * N_ITEMS) / CLS_GRID;
    const int NST   = (end - start) * 8;

    uint32_t aBase[4];
#pragma unroll
    for (int mi = 0; mi < 4; ++mi)
        aBase[mi] = sb + CLS_A_OFF
                  + (wm * 64 + mi * 16 + (lane & 15)) * AS_LDB
                  + (lane >> 4) * 16;
    uint32_t bBase[4];
#pragma unroll
    for (int ng = 0; ng < 4; ++ng)
        bBase[ng] = sb + CLS_B_OFF + (lane & 15) * BS_LDB
                  + (wn * 64 + ng * 16) * 2 + (lane >> 4) * 16;

    auto issue_stage = [&](int gs) {
        const int item = start + (gs >> 3);
        const int k0 = (gs & 7) * 32;
        const int v0 = (item % N_VT) * CLS_BN;
        const uint32_t dbase = sb + CLS_B_OFF + (gs & 3) * CLS_B_TILE;
#pragma unroll
        for (int i = 0; i < 4; ++i) {
            int c = tid + i * 128;
            int row = c >> 4, col = c & 15;
            CP_ASYNC16(dbase + row * BS_LDB + col * 16,
                       (const char*)(g_wob + (size_t)(k0 + row) * V_
                                     + v0 + col * 8));
        }
    };

#pragma unroll
    for (int st = 0; st < 3; ++st) { issue_stage(st); CP_COMMIT(); }

    float rAcc[4][2];
#pragma unroll
    for (int mi = 0; mi < 4; ++mi) { rAcc[mi][0] = 0.f; rAcc[mi][1] = 0.f; }

    float acc[4][8][4];
#pragma unroll
    for (int mi = 0; mi < 4; ++mi)
#pragma unroll
        for (int ni = 0; ni < 8; ++ni)
#pragma unroll
            for (int j = 0; j < 4; ++j) acc[mi][ni][j] = 0.0f;

    int cur_rb = -1;

    auto flush = [&](int rb) {
#pragma unroll
        for (int mi = 0; mi < 4; ++mi)
#pragma unroll
            for (int hi = 0; hi < 2; ++hi) {
                float v = rAcc[mi][hi];
                v += __shfl_xor_sync(0xFFFFFFFFu, v, 1);
                v += __shfl_xor_sync(0xFFFFFFFFu, v, 2);
                if ((lane & 3) == 0)
                    atomicAdd(&g_rowsum[rb * CLS_BM + wm * 64 + mi * 16
                                        + hi * 8 + (lane >> 2)], v);
                rAcc[mi][hi] = 0.0f;
            }
    };

    for (int gs = 0; gs < NST; ++gs) {
        CP_WAIT2();
        __syncthreads();
        if (gs + 3 < NST) issue_stage(gs + 3);
        CP_COMMIT();

        const int item = start + (gs >> 3);
        if ((gs & 7) == 0) {
            const int rb = item / N_VT;
            if (rb != cur_rb) {
                if (cur_rb >= 0) flush(cur_rb);
                const __nv_bfloat16* src = g_featb + (size_t)rb * CLS_BM * LAB_;
#pragma unroll
                for (int t = tid; t < CLS_BM * 32; t += 128) {
                    int r = t >> 5, k8 = t & 31;
                    uint4 v = *(const uint4*)&src[(size_t)r * LAB_ + k8 * 8];
                    *(uint4*)(smem + CLS_A_OFF + r * AS_LDB + k8 * 16) = v;
                }
                __syncthreads();
                cur_rb = rb;
            }
        }

        const uint32_t bufOff = (gs & 3) * CLS_B_TILE;
        const uint32_t aOff = (gs & 7) * 64;
#pragma unroll
        for (int s = 0; s < 2; ++s) {
            uint32_t a[4][4], bb[4][4];
#pragma unroll
            for (int mi = 0; mi < 4; ++mi)
                ldsm_x4(a[mi], aBase[mi] + aOff + s * 32);
#pragma unroll
            for (int ng = 0; ng < 4; ++ng)
                ldsm_x4_t(bb[ng], bBase[ng] + bufOff + s * 16 * BS_LDB);
#pragma unroll
            for (int mi = 0; mi < 4; ++mi)
#pragma unroll
                for (int ni = 0; ni < 8; ++ni)
                    mma_bf16(acc[mi][ni], a[mi],
                             bb[ni >> 1][(ni & 1) * 2],
                             bb[ni >> 1][(ni & 1) * 2 + 1]);
        }

        if ((gs & 7) == 7) {
            const int v0 = (item % N_VT) * CLS_BN;
            const float* bop = bo + v0 + wn * 64 + (lane & 3) * 2;
#pragma unroll
            for (int ni = 0; ni < 8; ++ni) {
                float2 bv = *(const float2*)(bop + ni * 8);
                float b0 = bv.x * LOG2E, b1 = bv.y * LOG2E;
#pragma unroll
                for (int mi = 0; mi < 4; ++mi) {
                    rAcc[mi][0] += ex2f(fmaf(acc[mi][ni][0], LOG2E, b0))
                                 + ex2f(fmaf(acc[mi][ni][1], LOG2E, b1));
                    rAcc[mi][1] += ex2f(fmaf(acc[mi][ni][2], LOG2E, b0))
                                 + ex2f(fmaf(acc[mi][ni][3], LOG2E, b1));
                    acc[mi][ni][0] = 0.f; acc[mi][ni][1] = 0.f;
                    acc[mi][ni][2] = 0.f; acc[mi][ni][3] = 0.f;
                }
            }
        }
    }
    CP_WAITALL();
    if (cur_rb >= 0) flush(cur_rb);
}

// ---------------------------------------------------------------------------
// loss: per-row fp32 tag logit + log(rowsum) + global sum
// ---------------------------------------------------------------------------
__global__ void loss_kernel(const float* __restrict__ Wo,
                            const float* __restrict__ bo,
                            const int* __restrict__ tags,
                            float* __restrict__ out) {
    const int warp = (blockIdx.x * blockDim.x + threadIdx.x) >> 5;
    const int lane = threadIdx.x & 31;
    const int nwarps = (gridDim.x * blockDim.x) >> 5;
    float local = 0.0f;
    for (int l = warp; l < L_; l += nwarps) {
        int tag = tags[l];
        float dot = 0.0f;
#pragma unroll
        for (int j = 0; j < 8; ++j) {
            int k = lane + j * 32;
            dot += g_feat[(size_t)l * 256 + k] * Wo[(size_t)k * V_ + tag];
        }
#pragma unroll
        for (int off = 16; off > 0; off >>= 1)
            dot += __shfl_down_sync(0xFFFFFFFFu, dot, off);
        if (lane == 0)
            local += logf(g_rowsum[l]) - (dot + bo[tag]);
    }
    if (lane == 0)
        atomicAdd(out, local * (1.0f / (4096.0f + 1e-5f)));
}

// ---------------------------------------------------------------------------
// Launch. Inputs: hidden, begins, ends, bids, tags, W1, b1, W2, b2, Wo, bo
// ---------------------------------------------------------------------------
extern "C" void kernel_launch(void* const* d_in, const int* in_sizes, int n_in,
                              void* d_out, int out_size) {
    const float* hidden = (const float*)d_in[0];
    const int*   begins = (const int*)d_in[1];
    const int*   ends   = (const int*)d_in[2];
    const int*   bids   = (const int*)d_in[3];
    const int*   tags   = (const int*)d_in[4];
    const float* W1     = (const float*)d_in[5];
    const float* b1     = (const float*)d_in[6];
    const float* W2     = (const float*)d_in[7];
    const float* b2     = (const float*)d_in[8];
    const float* Wo     = (const float*)d_in[9];
    const float* bo     = (const float*)d_in[10];
    float* out = (float*)d_out;

    __nv_bfloat16 *spanb, *h1b, *featb, *w1b, *w2b, *wob;
    float* feat;
    cudaGetSymbolAddress((void**)&spanb, g_spanb);
    cudaGetSymbolAddress((void**)&h1b, g_h1b);
    cudaGetSymbolAddress((void**)&feat, g_feat);
    cudaGetSymbolAddress((void**)&featb, g_featb);
    cudaGetSymbolAddress((void**)&w1b, g_w1b);
    cudaGetSymbolAddress((void**)&w2b, g_w2b);
    cudaGetSymbolAddress((void**)&wob, g_wob);

    // opt-in dynamic smem (ALL kernels over the 48KB default)
    cudaFuncSetAttribute(wgemm_kernel<3 * H_, 1>,
                         cudaFuncAttributeMaxDynamicSharedMemorySize,
                         WG_SMEM_BYTES);
    cudaFuncSetAttribute(wgemm_kernel<LAB_, 2>,
                         cudaFuncAttributeMaxDynamicSharedMemorySize,
                         WG_SMEM_BYTES);
    cudaFuncSetAttribute(cls_kernel,
                         cudaFuncAttributeMaxDynamicSharedMemorySize,
                         CLS_SMEM);

    // weight prep (bf16) + zero out + zero rowsums
    prep_kernel<<<(N1_4 + N2_4 + 255) / 256, 256>>>(W1, W2, out);
    cvt_kernel<<<(LAB_ * V_ / 4 + 255) / 256, 256>>>(Wo, wob, LAB_ * V_ / 4);

    // 1) span embeddings (bf16)
    span_kernel<<<L_, 128>>>(hidden, begins, ends, bids);

    // 2) h1 = sigmoid(span @ W1 + b1) -> bf16
    {
        dim3 grid(L_ / 128, LAB_ / 64);
        wgemm_kernel<3 * H_, 1><<<grid, 128, WG_SMEM_BYTES>>>(
            spanb, w1b, b1, nullptr, h1b, LAB_);
    }
    // 3) feat = h1 @ W2 + b2 -> fp32 + bf16
    {
        dim3 grid(L_ / 128, LAB_ / 64);
        wgemm_kernel<LAB_, 2><<<grid, 128, WG_SMEM_BYTES>>>(
            h1b, w2b, b2, feat, featb, LAB_);
    }
    // 4) persistent mma.sync classifier GEMM + fused exp-sum
    cls_kernel<<<CLS_GRID, 128, CLS_SMEM>>>(bo);

    // 5) final loss reduction
    loss_kernel<<<32, 256>>>(Wo, bo, tags, out);
}

// round 14
// speedup vs baseline: 1.5279x; 1.0170x over previous
#include <cuda_runtime.h>
#include <cuda_bf16.h>
#include <math.h>
#include <stdint.h>

// Problem constants
#define S_    2048
#define B_    16
#define H_    512
#define L_    4096
#define LAB_  256
#define V_    32000

// cls: persistent grid, rowblock-major work items, 128 threads (4 warps 2x2)
#define CLS_BM    128
#define CLS_BN    128
#define CLS_GRID  296                 // 2 CTAs x 148 SMs, one wave
#define N_RB      (L_ / CLS_BM)       // 32 rowblocks
#define N_VT      (V_ / CLS_BN)       // 250 v-tiles
#define N_ITEMS   (N_RB * N_VT)       // 8000

// cls smem (bytes)
#define AS_LDB   528                  // A row stride bytes (264 bf16)
#define BS_LDB   272                  // B row stride bytes (136 bf16)
#define CLS_A_OFF 0
#define CLS_A_BYTES (CLS_BM * AS_LDB)        // 67584
#define CLS_B_OFF  CLS_A_BYTES
#define CLS_B_TILE (32 * BS_LDB)             // 8704
#define CLS_B_BYTES (4 * CLS_B_TILE)         // 34816 (4-stage ring)
#define CLS_SMEM (CLS_B_OFF + CLS_B_BYTES)   // 102400 -> 2 CTAs/SM

// wgemm (raw mma): BM=64, BN=64, 128 threads (2x2 warps, 32x32 tiles)
#define WGA_LDB 80                    // A row stride bytes (32 bf16 + 16B pad)
#define WGB_LDB 144                   // B row stride bytes (64 bf16 + pad)
#define WG_A_BYTES (64 * WGA_LDB)     // 5120
#define WG_STAGE (WG_A_BYTES + 32 * WGB_LDB) // 9728
#define WG_SMEM_BYTES (4 * WG_STAGE)  // 38912 (under 48KB default)

// Scratch (static device globals)
__device__ __nv_bfloat16 g_spanb[(size_t)L_ * 3 * H_];
__device__ __nv_bfloat16 g_h1b[(size_t)L_ * LAB_];
__device__ float g_feat[(size_t)L_ * LAB_];
__device__ __nv_bfloat16 g_featb[(size_t)L_ * LAB_];
__device__ __nv_bfloat16 g_w1b[(size_t)3 * H_ * LAB_];
__device__ __nv_bfloat16 g_w2b[(size_t)LAB_ * LAB_];
__device__ __nv_bfloat16 g_wob[(size_t)LAB_ * V_];      // Wo bf16 [256][32000]
__device__ float g_rowsum[L_];                          // per-row exp sums

// ---------------------------------------------------------------------------
// PTX primitives (sm80-baseline)
// ---------------------------------------------------------------------------
__device__ __forceinline__ uint32_t smem_u32(const void* p) {
    uint32_t a;
    asm("{ .reg .u64 t; cvta.to.shared.u64 t, %1; cvt.u32.u64 %0, t; }"
        : "=r"(a) : "l"(p));
    return a;
}
__device__ __forceinline__ void ldsm_x4(uint32_t r[4], uint32_t addr) {
    asm volatile("ldmatrix.sync.aligned.m8n8.x4.shared.b16 {%0,%1,%2,%3}, [%4];"
        : "=r"(r[0]), "=r"(r[1]), "=r"(r[2]), "=r"(r[3]) : "r"(addr));
}
__device__ __forceinline__ void ldsm_x4_t(uint32_t r[4], uint32_t addr) {
    asm volatile("ldmatrix.sync.aligned.m8n8.x4.trans.shared.b16 {%0,%1,%2,%3}, [%4];"
        : "=r"(r[0]), "=r"(r[1]), "=r"(r[2]), "=r"(r[3]) : "r"(addr));
}
__device__ __forceinline__ void mma_bf16(float d[4], const uint32_t a[4],
                                         uint32_t b0, uint32_t b1) {
    asm volatile(
        "mma.sync.aligned.m16n8k16.row.col.f32.bf16.bf16.f32 "
        "{%0,%1,%2,%3}, {%4,%5,%6,%7}, {%8,%9}, {%0,%1,%2,%3};"
        : "+f"(d[0]), "+f"(d[1]), "+f"(d[2]), "+f"(d[3])
        : "r"(a[0]), "r"(a[1]), "r"(a[2]), "r"(a[3]), "r"(b0), "r"(b1));
}
#define CP_ASYNC16(dst, src) \
    asm volatile("cp.async.cg.shared.global [%0], [%1], 16;" \
        :: "r"(dst), "l"(src) : "memory")
#define CP_COMMIT() asm volatile("cp.async.commit_group;" ::: "memory")
#define CP_WAIT2()  asm volatile("cp.async.wait_group 2;" ::: "memory")
#define CP_WAITALL() asm volatile("cp.async.wait_group 0;" ::: "memory")

__device__ __forceinline__ float ex2f(float x) {
    float r;
    asm("ex2.approx.f32 %0, %1;" : "=f"(r) : "f"(x));
    return r;
}

// ---------------------------------------------------------------------------
// fast exp poly (sigmoid epilogue in wgemm)
// ---------------------------------------------------------------------------
__device__ __forceinline__ float fast_exp(float x) {
    float z = x * 1.4426950408889634f;
    float r = rintf(z);
    float f = z - r;
    float p = 1.3333558146428443e-3f;
    p = fmaf(p, f, 9.6181291976036120e-3f);
    p = fmaf(p, f, 5.5504108664821580e-2f);
    p = fmaf(p, f, 2.4022650695910072e-1f);
    p = fmaf(p, f, 6.9314718055994531e-1f);
    p = fmaf(p, f, 1.0f);
    return __int_as_float(((int)r + 127) << 23) * p;
}

// ---------------------------------------------------------------------------
// span embeddings -> bf16 (float4, 4-way unrolled gather for MLP)
// ---------------------------------------------------------------------------
__global__ void span_kernel(const float* __restrict__ hidden,
                            const int* __restrict__ begins,
                            const int* __restrict__ ends,
                            const int* __restrict__ bids) {
    const int l = blockIdx.x;
    const int beg = begins[l];
    const int end = ends[l];
    const int b   = bids[l];
    const float inv_len = 1.0f / (float)(end - beg);
    const float4* hp = (const float4*)hidden;
    const int h4 = threadIdx.x;            // 0..127
    const int H4 = H_ / 4;

    float4 left  = hp[((size_t)(beg - 1) * B_ + b) * H4 + h4];
    float4 right = hp[((size_t)end * B_ + b) * H4 + h4];
    float4 s0 = make_float4(0.f, 0.f, 0.f, 0.f);
    float4 s1 = make_float4(0.f, 0.f, 0.f, 0.f);
    float4 s2 = make_float4(0.f, 0.f, 0.f, 0.f);
    float4 s3 = make_float4(0.f, 0.f, 0.f, 0.f);
    int t = beg;
    for (; t + 4 <= end; t += 4) {
        float4 v0 = hp[((size_t)t * B_ + b) * H4 + h4];
        float4 v1 = hp[((size_t)(t + 1) * B_ + b) * H4 + h4];
        float4 v2 = hp[((size_t)(t + 2) * B_ + b) * H4 + h4];
        float4 v3 = hp[((size_t)(t + 3) * B_ + b) * H4 + h4];
        s0.x += v0.x; s0.y += v0.y; s0.z += v0.z; s0.w += v0.w;
        s1.x += v1.x; s1.y += v1.y; s1.z += v1.z; s1.w += v1.w;
        s2.x += v2.x; s2.y += v2.y; s2.z += v2.z; s2.w += v2.w;
        s3.x += v3.x; s3.y += v3.y; s3.z += v3.z; s3.w += v3.w;
    }
    for (; t < end; ++t) {
        float4 v0 = hp[((size_t)t * B_ + b) * H4 + h4];
        s0.x += v0.x; s0.y += v0.y; s0.z += v0.z; s0.w += v0.w;
    }
    s0.x += s1.x + s2.x + s3.x;
    s0.y += s1.y + s2.y + s3.y;
    s0.z += s1.z + s2.z + s3.z;
    s0.w += s1.w + s2.w + s3.w;

    __nv_bfloat16* out = g_spanb + (size_t)l * (3 * H_);
    uint2 pk;
    pk.x = __nv_bfloat162_raw(__floats2bfloat162_rn(left.x, left.y)).x;
    pk.y = __nv_bfloat162_raw(__floats2bfloat162_rn(left.z, left.w)).x;
    *(uint2*)&out[h4 * 4] = pk;
    pk.x = __nv_bfloat162_raw(__floats2bfloat162_rn(s0.x * inv_len, s0.y * inv_len)).x;
    pk.y = __nv_bfloat162_raw(__floats2bfloat162_rn(s0.z * inv_len, s0.w * inv_len)).x;
    *(uint2*)&out[H_ + h4 * 4] = pk;
    pk.x = __nv_bfloat162_raw(__floats2bfloat162_rn(right.x, right.y)).x;
    pk.y = __nv_bfloat162_raw(__floats2bfloat162_rn(right.z, right.w)).x;
    *(uint2*)&out[2 * H_ + h4 * 4] = pk;
}

// ---------------------------------------------------------------------------
// prep: W1+W2 -> bf16, zero out + g_rowsum (fused launches)
// ---------------------------------------------------------------------------
#define N1_4 (3 * H_ * LAB_ / 4)
#define N2_4 (LAB_ * LAB_ / 4)
__global__ void prep_kernel(const float* __restrict__ W1,
                            const float* __restrict__ W2,
                            float* __restrict__ out) {
    int i = blockIdx.x * blockDim.x + threadIdx.x;
    if (i == 0) out[0] = 0.0f;
    if (i < L_) g_rowsum[i] = 0.0f;
    if (i < N1_4) {
        float4 v = ((const float4*)W1)[i];
        ((__nv_bfloat162*)g_w1b)[2 * i]     = __floats2bfloat162_rn(v.x, v.y);
        ((__nv_bfloat162*)g_w1b)[2 * i + 1] = __floats2bfloat162_rn(v.z, v.w);
    } else if (i < N1_4 + N2_4) {
        int j = i - N1_4;
        float4 v = ((const float4*)W2)[j];
        ((__nv_bfloat162*)g_w2b)[2 * j]     = __floats2bfloat162_rn(v.x, v.y);
        ((__nv_bfloat162*)g_w2b)[2 * j + 1] = __floats2bfloat162_rn(v.z, v.w);
    }
}

// ---------------------------------------------------------------------------
// fp32 -> bf16 conversion (Wo)
// ---------------------------------------------------------------------------
__global__ void cvt_kernel(const float* __restrict__ src,
                           __nv_bfloat16* __restrict__ dst, int n4) {
    int i = blockIdx.x * blockDim.x + threadIdx.x;
    if (i < n4) {
        float4 v = ((const float4*)src)[i];
        ((__nv_bfloat162*)dst)[2 * i]     = __floats2bfloat162_rn(v.x, v.y);
        ((__nv_bfloat162*)dst)[2 * i + 1] = __floats2bfloat162_rn(v.z, v.w);
    }
}

// ---------------------------------------------------------------------------
// wgemm (raw mma.sync): C[M,N] = epi(A[M,K] @ B[K,N] + bias)
// BM=64, BN=64, 128 threads = 4 warps (2x2), warp tile 32x32.
// 4-stage K=32 cp.async ring; direct register epilogue.
// EPI 1: sigmoid -> bf16 Cb. EPI 2: bias -> fp32 C32 AND bf16 Cb.
// grid (M/64, N/64) = (64, 4) = 256 CTAs.
// ---------------------------------------------------------------------------
template<int K, int EPI>
__global__ __launch_bounds__(128)
void wgemm_kernel(const __nv_bfloat16* __restrict__ A,
                  const __nv_bfloat16* __restrict__ B,
                  const float* __restrict__ bias,
                  float* __restrict__ C32,
                  __nv_bfloat16* __restrict__ Cb, int N) {
    extern __shared__ char smem[];
    const uint32_t sb = smem_u32(smem);

    const int tid = threadIdx.x;
    const int wid = tid >> 5;
    const int lane = tid & 31;
    const int wm = wid >> 1;     // 0..1 (row group of 32)
    const int wn = wid & 1;      // 0..1 (col group of 32)
    const int m0 = blockIdx.x * 64;
    const int n0 = blockIdx.y * 64;
    constexpr int NIT = K / 32;

    auto issue = [&](int g) {
        const int k0 = g * 32;
        const uint32_t st = sb + (g & 3) * WG_STAGE;
        // A: 64 rows x 32 bf16 = 256 x 16B chunks, 2 per thread
#pragma unroll
        for (int i = 0; i < 2; ++i) {
            int c = tid + i * 128;
            int r = c >> 2, kc = c & 3;
            CP_ASYNC16(st + r * WGA_LDB + kc * 16,
                       (const char*)&A[(size_t)(m0 + r) * K + k0 + kc * 8]);
        }
        // B: 32 k-rows x 64 cols = 256 x 16B chunks, 2 per thread
#pragma unroll
        for (int i = 0; i < 2; ++i) {
            int c = tid + i * 128;
            int rk = c >> 3, cc = c & 7;
            CP_ASYNC16(st + WG_A_BYTES + rk * WGB_LDB + cc * 16,
                       (const char*)&B[(size_t)(k0 + rk) * N + n0 + cc * 8]);
        }
    };

    uint32_t aBase[2];
#pragma unroll
    for (int mi = 0; mi < 2; ++mi)
        aBase[mi] = sb + (wm * 32 + mi * 16 + (lane & 15)) * WGA_LDB
                  + (lane >> 4) * 16;
    uint32_t bBase[2];
#pragma unroll
    for (int ng = 0; ng < 2; ++ng)
        bBase[ng] = sb + WG_A_BYTES + (lane & 15) * WGB_LDB
                  + (wn * 32 + ng * 16) * 2 + (lane >> 4) * 16;

    float acc[2][4][4];
#pragma unroll
    for (int mi = 0; mi < 2; ++mi)
#pragma unroll
        for (int ni = 0; ni < 4; ++ni)
#pragma unroll
            for (int j = 0; j < 4; ++j) acc[mi][ni][j] = 0.0f;

#pragma unroll
    for (int st = 0; st < 3; ++st) { issue(st); CP_COMMIT(); }

    for (int g = 0; g < NIT; ++g) {
        CP_WAIT2();
        __syncthreads();
        if (g + 3 < NIT) issue(g + 3);
        CP_COMMIT();
        const uint32_t stOff = (g & 3) * WG_STAGE;
#pragma unroll
        for (int s = 0; s < 2; ++s) {
            uint32_t a[2][4], bb[2][4];
#pragma unroll
            for (int mi = 0; mi < 2; ++mi)
                ldsm_x4(a[mi], aBase[mi] + stOff + s * 32);
#pragma unroll
            for (int ng = 0; ng < 2; ++ng)
                ldsm_x4_t(bb[ng], bBase[ng] + stOff + s * 16 * WGB_LDB);
#pragma unroll
            for (int mi = 0; mi < 2; ++mi)
#pragma unroll
                for (int ni = 0; ni < 4; ++ni)
                    mma_bf16(acc[mi][ni], a[mi],
                             bb[ni >> 1][(ni & 1) * 2],
                             bb[ni >> 1][(ni & 1) * 2 + 1]);
        }
        __syncthreads();
    }
    CP_WAITALL();

    // direct register epilogue (m16n8k16 acc lane mapping)
#pragma unroll
    for (int mi = 0; mi < 2; ++mi) {
        const int r0 = m0 + wm * 32 + mi * 16 + (lane >> 2);
#pragma unroll
        for (int ni = 0; ni < 4; ++ni) {
            const int gc = n0 + wn * 32 + ni * 8 + (lane & 3) * 2;
            float2 bv = *(const float2*)&bias[gc];
            float v00 = acc[mi][ni][0] + bv.x;
            float v01 = acc[mi][ni][1] + bv.y;
            float v10 = acc[mi][ni][2] + bv.x;
            float v11 = acc[mi][ni][3] + bv.y;
            if (EPI == 1) {
                v00 = 1.0f / (1.0f + fast_exp(-v00));
                v01 = 1.0f / (1.0f + fast_exp(-v01));
                v10 = 1.0f / (1.0f + fast_exp(-v10));
                v11 = 1.0f / (1.0f + fast_exp(-v11));
                *(__nv_bfloat162*)&Cb[(size_t)r0 * N + gc] =
                    __floats2bfloat162_rn(v00, v01);
                *(__nv_bfloat162*)&Cb[(size_t)(r0 + 8) * N + gc] =
                    __floats2bfloat162_rn(v10, v11);
            } else {
                *(float2*)&C32[(size_t)r0 * N + gc] = make_float2(v00, v01);
                *(float2*)&C32[(size_t)(r0 + 8) * N + gc] = make_float2(v10, v11);
                *(__nv_bfloat162*)&Cb[(size_t)r0 * N + gc] =
                    __floats2bfloat162_rn(v00, v01);
                *(__nv_bfloat162*)&Cb[(size_t)(r0 + 8) * N + gc] =
                    __floats2bfloat162_rn(v10, v11);
            }
        }
    }
}

// ---------------------------------------------------------------------------
// cls: PERSISTENT mma.sync bf16 classifier GEMM + fused per-row exp-sums.
// 128 threads = 4 warps, 2x2 grid of 64x64 warp tiles.
// grid = 296 (2 CTAs/SM). Work = 8000 items (rb, vtile), rowblock-major.
// ---------------------------------------------------------------------------
__global__ __launch_bounds__(128, 2)
void cls_kernel(const float* __restrict__ bo) {
    extern __shared__ char smem[];
    const uint32_t sb = smem_u32(smem);

    const int tid = threadIdx.x;
    const int wid = tid >> 5;
    const int lane = tid & 31;
    const int wm = wid >> 1;          // 0..1 (row group of 64)
    const int wn = wid & 1;           // 0..1 (col group of 64)
    const float LOG2E = 1.4426950408889634f;

    const int start = (blockIdx.x * N_ITEMS) / CLS_GRID;
    const int end   = ((blockIdx.x + 1) * N_ITEMS) / CLS_GRID;
    const int NST   = (end - start) * 8;

    uint32_t aBase[4];
#pragma unroll
    for (int mi = 0; mi < 4; ++mi)
        aBase[mi] = sb + CLS_A_OFF
                  + (wm * 64 + mi * 16 + (lane & 15)) * AS_LDB
                  + (lane >> 4) * 16;
    uint32_t bBase[4];
#pragma unroll
    for (int ng = 0; ng < 4; ++ng)
        bBase[ng] = sb + CLS_B_OFF + (lane & 15) * BS_LDB
                  + (wn * 64 + ng * 16) * 2 + (lane >> 4) * 16;

    auto issue_stage = [&](int gs) {
        const int item = start + (gs >> 3);
        const int k0 = (gs & 7) * 32;
        const int v0 = (item % N_VT) * CLS_BN;
        const uint32_t dbase = sb + CLS_B_OFF + (gs & 3) * CLS_B_TILE;
#pragma unroll
        for (int i = 0; i < 4; ++i) {
            int c = tid + i * 128;
            int row = c >> 4, col = c & 15;
            CP_ASYNC16(dbase + row * BS_LDB + col * 16,
                       (const char*)(g_wob + (size_t)(k0 + row) * V_
                                     + v0 + col * 8));
        }
    };

#pragma unroll
    for (int st = 0; st < 3; ++st) { issue_stage(st); CP_COMMIT(); }

    float rAcc[4][2];
#pragma unroll
    for (int mi = 0; mi < 4; ++mi) { rAcc[mi][0] = 0.f; rAcc[mi][1] = 0.f; }

    float acc[4][8][4];
#pragma unroll
    for (int mi = 0; mi < 4; ++mi)
#pragma unroll
        for (int ni = 0; ni < 8; ++ni)
#pragma unroll
            for (int j = 0; j < 4; ++j) acc[mi][ni][j] = 0.0f;

    int cur_rb = -1;

    auto flush = [&](int rb) {
#pragma unroll
        for (int mi = 0; mi < 4; ++mi)
#pragma unroll
            for (int hi = 0; hi < 2; ++hi) {
                float v = rAcc[mi][hi];
                v += __shfl_xor_sync(0xFFFFFFFFu, v, 1);
                v += __shfl_xor_sync(0xFFFFFFFFu, v, 2);
                if ((lane & 3) == 0)
                    atomicAdd(&g_rowsum[rb * CLS_BM + wm * 64 + mi * 16
                                        + hi * 8 + (lane >> 2)], v);
                rAcc[mi][hi] = 0.0f;
            }
    };

    for (int gs = 0; gs < NST; ++gs) {
        CP_WAIT2();
        __syncthreads();
        if (gs + 3 < NST) issue_stage(gs + 3);
        CP_COMMIT();

        const int item = start + (gs >> 3);
        if ((gs & 7) == 0) {
            const int rb = item / N_VT;
            if (rb != cur_rb) {
                if (cur_rb >= 0) flush(cur_rb);
                const __nv_bfloat16* src = g_featb + (size_t)rb * CLS_BM * LAB_;
#pragma unroll
                for (int t = tid; t < CLS_BM * 32; t += 128) {
                    int r = t >> 5, k8 = t & 31;
                    uint4 v = *(const uint4*)&src[(size_t)r * LAB_ + k8 * 8];
                    *(uint4*)(smem + CLS_A_OFF + r * AS_LDB + k8 * 16) = v;
                }
                __syncthreads();
                cur_rb = rb;
            }
        }

        const uint32_t bufOff = (gs & 3) * CLS_B_TILE;
        const uint32_t aOff = (gs & 7) * 64;
#pragma unroll
        for (int s = 0; s < 2; ++s) {
            uint32_t a[4][4], bb[4][4];
#pragma unroll
            for (int mi = 0; mi < 4; ++mi)
                ldsm_x4(a[mi], aBase[mi] + aOff + s * 32);
#pragma unroll
            for (int ng = 0; ng < 4; ++ng)
                ldsm_x4_t(bb[ng], bBase[ng] + bufOff + s * 16 * BS_LDB);
#pragma unroll
            for (int mi = 0; mi < 4; ++mi)
#pragma unroll
                for (int ni = 0; ni < 8; ++ni)
                    mma_bf16(acc[mi][ni], a[mi],
                             bb[ni >> 1][(ni & 1) * 2],
                             bb[ni >> 1][(ni & 1) * 2 + 1]);
        }

        if ((gs & 7) == 7) {
            const int v0 = (item % N_VT) * CLS_BN;
            const float* bop = bo + v0 + wn * 64 + (lane & 3) * 2;
#pragma unroll
            for (int ni = 0; ni < 8; ++ni) {
                float2 bv = *(const float2*)(bop + ni * 8);
                float b0 = bv.x * LOG2E, b1 = bv.y * LOG2E;
#pragma unroll
                for (int mi = 0; mi < 4; ++mi) {
                    rAcc[mi][0] += ex2f(fmaf(acc[mi][ni][0], LOG2E, b0))
                                 + ex2f(fmaf(acc[mi][ni][1], LOG2E, b1));
                    rAcc[mi][1] += ex2f(fmaf(acc[mi][ni][2], LOG2E, b0))
                                 + ex2f(fmaf(acc[mi][ni][3], LOG2E, b1));
                    acc[mi][ni][0] = 0.f; acc[mi][ni][1] = 0.f;
                    acc[mi][ni][2] = 0.f; acc[mi][ni][3] = 0.f;
                }
            }
        }
    }
    CP_WAITALL();
    if (cur_rb >= 0) flush(cur_rb);
}

// ---------------------------------------------------------------------------
// loss: per-row fp32 tag logit + log(rowsum) + global sum
// ---------------------------------------------------------------------------
__global__ void loss_kernel(const float* __restrict__ Wo,
                            const float* __restrict__ bo,
                            const int* __restrict__ tags,
                            float* __restrict__ out) {
    const int warp = (blockIdx.x * blockDim.x + threadIdx.x) >> 5;
    const int lane = threadIdx.x & 31;
    const int nwarps = (gridDim.x * blockDim.x) >> 5;
    float local = 0.0f;
    for (int l = warp; l < L_; l += nwarps) {
        int tag = tags[l];
        float dot = 0.0f;
#pragma unroll
        for (int j = 0; j < 8; ++j) {
            int k = lane + j * 32;
            dot += g_feat[(size_t)l * 256 + k] * Wo[(size_t)k * V_ + tag];
        }
#pragma unroll
        for (int off = 16; off > 0; off >>= 1)
            dot += __shfl_down_sync(0xFFFFFFFFu, dot, off);
        if (lane == 0)
            local += logf(g_rowsum[l]) - (dot + bo[tag]);
    }
    if (lane == 0)
        atomicAdd(out, local * (1.0f / (4096.0f + 1e-5f)));
}

// ---------------------------------------------------------------------------
// Launch. Inputs: hidden, begins, ends, bids, tags, W1, b1, W2, b2, Wo, bo
// ---------------------------------------------------------------------------
extern "C" void kernel_launch(void* const* d_in, const int* in_sizes, int n_in,
                              void* d_out, int out_size) {
    const float* hidden = (const float*)d_in[0];
    const int*   begins = (const int*)d_in[1];
    const int*   ends   = (const int*)d_in[2];
    const int*   bids   = (const int*)d_in[3];
    const int*   tags   = (const int*)d_in[4];
    const float* W1     = (const float*)d_in[5];
    const float* b1     = (const float*)d_in[6];
    const float* W2     = (const float*)d_in[7];
    const float* b2     = (const float*)d_in[8];
    const float* Wo     = (const float*)d_in[9];
    const float* bo     = (const float*)d_in[10];
    float* out = (float*)d_out;

    __nv_bfloat16 *spanb, *h1b, *featb, *w1b, *w2b, *wob;
    float* feat;
    cudaGetSymbolAddress((void**)&spanb, g_spanb);
    cudaGetSymbolAddress((void**)&h1b, g_h1b);
    cudaGetSymbolAddress((void**)&feat, g_feat);
    cudaGetSymbolAddress((void**)&featb, g_featb);
    cudaGetSymbolAddress((void**)&w1b, g_w1b);
    cudaGetSymbolAddress((void**)&w2b, g_w2b);
    cudaGetSymbolAddress((void**)&wob, g_wob);

    // opt-in dynamic smem (cls only; wgemm fits the 48KB default)
    cudaFuncSetAttribute(cls_kernel,
                         cudaFuncAttributeMaxDynamicSharedMemorySize,
                         CLS_SMEM);

    // weight prep (bf16) + zero out + zero rowsums
    prep_kernel<<<(N1_4 + N2_4 + 255) / 256, 256>>>(W1, W2, out);
    cvt_kernel<<<(LAB_ * V_ / 4 + 255) / 256, 256>>>(Wo, wob, LAB_ * V_ / 4);

    // 1) span embeddings (bf16)
    span_kernel<<<L_, 128>>>(hidden, begins, ends, bids);

    // 2) h1 = sigmoid(span @ W1 + b1) -> bf16
    {
        dim3 grid(L_ / 64, LAB_ / 64);
        wgemm_kernel<3 * H_, 1><<<grid, 128, WG_SMEM_BYTES>>>(
            spanb, w1b, b1, nullptr, h1b, LAB_);
    }
    // 3) feat = h1 @ W2 + b2 -> fp32 + bf16
    {
        dim3 grid(L_ / 64, LAB_ / 64);
        wgemm_kernel<LAB_, 2><<<grid, 128, WG_SMEM_BYTES>>>(
            h1b, w2b, b2, feat, featb, LAB_);
    }
    // 4) persistent mma.sync classifier GEMM + fused exp-sum
    cls_kernel<<<CLS_GRID, 128, CLS_SMEM>>>(bo);

    // 5) final loss reduction
    loss_kernel<<<32, 256>>>(Wo, bo, tags, out);
}